// round 1
// baseline (speedup 1.0000x reference)
#include <cuda_runtime.h>
#include <math.h>

#define HW   16384
#define HH   128
#define WW   128
#define NB   4

// ---------------- scratch (device globals; no allocations allowed) ----------
__device__ float g_qkv  [NB * 192 * HW];   // conv qkv output
__device__ float g_qkvdw[NB * 192 * HW];   // after depthwise 3x3
__device__ float g_a    [NB * 64  * HW];   // swish(a1) output
__device__ float g_cat  [NB * 128 * HW];   // [res_h | res_l]
__device__ float g_qg   [NB * 64  * HW];   // low-freq Q
__device__ float g_xp   [NB * 128 * 256];  // avgpooled x
__device__ float g_kv   [NB * 128 * 256];  // low-freq K|V

// ---------------- generic conv1x1 GEMM: dst[oc,p] = sum_c W[oc,c]*X[c,p] ----
// Block tile: 64 oc x 128 pixels, K-chunk 16. 256 threads, micro-tile 8x4.
// EPI: 0 = none, 1 = swish (x*sigmoid(x)), 2 = tanh(x*0.25)*vaux
// MUL: X[c,p] = src[c,p]*src[c,p + src2_off]   (fuses the q*k product)
template<int EPI, bool MUL>
__global__ void __launch_bounds__(256) conv_gemm(
    const float* __restrict__ src, int src_bstride, int src2_off,
    const float* __restrict__ Wt, const float* __restrict__ bias, int IC,
    float* __restrict__ dst, int dst_bstride, int dst_oc_base,
    const float* __restrict__ vaux, int vaux_bstride, int vaux_oc_base,
    int NPIX)
{
    const int tid = threadIdx.x;
    const int tx  = tid & 31;        // pixel group: pixels tx*4 .. tx*4+3
    const int ty  = tid >> 5;        // oc group:    ocs    ty*8 .. ty*8+7
    const int p0  = blockIdx.x * 128;
    const int oc0 = blockIdx.y * 64;
    const int b   = blockIdx.z;

    __shared__ __align__(16) float Ws[64][16];
    __shared__ __align__(16) float Xs[16][128];

    const float* srcb = src + (size_t)b * src_bstride;

    float acc[8][4];
    #pragma unroll
    for (int i = 0; i < 8; i++)
        #pragma unroll
        for (int j = 0; j < 4; j++) acc[i][j] = 0.f;

    for (int k0 = 0; k0 < IC; k0 += 16) {
        // ---- load W tile (64 oc x 16 k): coalesced over k
        {
            const int kk  = tid & 15;
            const int ocl = tid >> 4;          // 16 ocs per pass
            #pragma unroll
            for (int r = 0; r < 4; r++)
                Ws[ocl + r * 16][kk] = __ldg(&Wt[(size_t)(oc0 + ocl + r * 16) * IC + k0 + kk]);
        }
        // ---- load X tile (16 k x 128 pixels): coalesced over pixels
        {
            const int p   = tid & 127;
            const int kk0 = tid >> 7;          // 2 rows per pass
            #pragma unroll
            for (int r = 0; r < 8; r++) {
                const int kk = kk0 + r * 2;
                const float* sp = srcb + (size_t)(k0 + kk) * NPIX + p0 + p;
                float v = __ldg(sp);
                if (MUL) v *= __ldg(sp + src2_off);
                Xs[kk][p] = v;
            }
        }
        __syncthreads();

        #pragma unroll
        for (int kk = 0; kk < 16; kk++) {
            const float4 xv = *reinterpret_cast<const float4*>(&Xs[kk][tx * 4]);
            #pragma unroll
            for (int i = 0; i < 8; i++) {
                const float wv = Ws[ty * 8 + i][kk];
                acc[i][0] += wv * xv.x;
                acc[i][1] += wv * xv.y;
                acc[i][2] += wv * xv.z;
                acc[i][3] += wv * xv.w;
            }
        }
        __syncthreads();
    }

    // ---- epilogue
    float* dstb = dst + (size_t)b * dst_bstride;
    const float* vb = (EPI == 2) ? (vaux + (size_t)b * vaux_bstride) : nullptr;

    #pragma unroll
    for (int i = 0; i < 8; i++) {
        const int oc = oc0 + ty * 8 + i;
        const float bv = __ldg(&bias[oc]);
        float* drow = dstb + (size_t)(dst_oc_base + oc) * NPIX + p0 + tx * 4;
        float4 o;
        float v[4];
        #pragma unroll
        for (int j = 0; j < 4; j++) v[j] = acc[i][j] + bv;
        if (EPI == 1) {
            #pragma unroll
            for (int j = 0; j < 4; j++) v[j] = v[j] / (1.f + __expf(-v[j]));
        } else if (EPI == 2) {
            const float* vrow = vb + (size_t)(vaux_oc_base + oc) * NPIX + p0 + tx * 4;
            #pragma unroll
            for (int j = 0; j < 4; j++) v[j] = tanhf(v[j] * 0.25f) * __ldg(&vrow[j]);
        }
        o.x = v[0]; o.y = v[1]; o.z = v[2]; o.w = v[3];
        *reinterpret_cast<float4*>(drow) = o;
    }
}

// ---------------- depthwise 3x3 SAME (zero pad) -----------------------------
__global__ void dwconv3_kernel(const float* __restrict__ src,
                               const float* __restrict__ w,
                               const float* __restrict__ bias,
                               float* __restrict__ dst)
{
    const int plane = blockIdx.z;            // b*192 + c
    const int c = plane % 192;
    const int x = blockIdx.x * 32 + threadIdx.x;
    const int y = blockIdx.y * 8 + threadIdx.y;
    const float* sp = src + (size_t)plane * HW;

    float wk[9];
    #pragma unroll
    for (int i = 0; i < 9; i++) wk[i] = __ldg(&w[c * 9 + i]);

    float s = __ldg(&bias[c]);
    #pragma unroll
    for (int dy = -1; dy <= 1; dy++) {
        const int yy = y + dy;
        if (yy < 0 || yy >= HH) continue;
        #pragma unroll
        for (int dx = -1; dx <= 1; dx++) {
            const int xx = x + dx;
            if (xx < 0 || xx >= WW) continue;
            s += wk[(dy + 1) * 3 + (dx + 1)] * __ldg(&sp[yy * WW + xx]);
        }
    }
    dst[(size_t)plane * HW + y * WW + x] = s;
}

// ---------------- 8x8 avgpool: (B,128,128,128) -> (B,128,16,16) -------------
__global__ void avgpool8(const float* __restrict__ x, float* __restrict__ xp)
{
    const int idx = blockIdx.x * 256 + threadIdx.x;   // NB*128*256 outputs
    const int pos = idx & 255;
    const int j = pos & 15, i = pos >> 4;
    const int bc = idx >> 8;
    const float* sp = x + (size_t)bc * HW + (i * 8) * WW + j * 8;
    float s = 0.f;
    #pragma unroll
    for (int r = 0; r < 8; r++) {
        const float4 a = *reinterpret_cast<const float4*>(sp + r * WW);
        const float4 b = *reinterpret_cast<const float4*>(sp + r * WW + 4);
        s += a.x + a.y + a.z + a.w + b.x + b.y + b.z + b.w;
    }
    xp[idx] = s * (1.f / 64.f);
}

// ---------------- low-freq softmax attention --------------------------------
// grid (HW/128, heads=4, B); block 128 threads; each thread = one query pixel.
__global__ void __launch_bounds__(128) lowfreq_attn(
    const float* __restrict__ qg, const float* __restrict__ kv,
    float* __restrict__ cat)
{
    const int b = blockIdx.z, h = blockIdx.y;
    const int p = blockIdx.x * 128 + threadIdx.x;

    __shared__ float ks[256][16];
    __shared__ float vs[256][16];

    const float* kvb = kv + (size_t)b * 128 * 256;
    for (int i = threadIdx.x; i < 4096; i += 128) {
        const int d = i >> 8, m = i & 255;
        ks[m][d] = kvb[(h * 16 + d) * 256 + m];
        vs[m][d] = kvb[(64 + h * 16 + d) * 256 + m];
    }
    __syncthreads();

    float q[16];
    #pragma unroll
    for (int d = 0; d < 16; d++)
        q[d] = __ldg(&qg[(size_t)b * 64 * HW + (size_t)(h * 16 + d) * HW + p]);

    float mx = -1e30f, sum = 0.f;
    float acc[16];
    #pragma unroll
    for (int d = 0; d < 16; d++) acc[d] = 0.f;

    for (int m = 0; m < 256; m++) {
        float s = 0.f;
        #pragma unroll
        for (int d = 0; d < 16; d++) s += q[d] * ks[m][d];
        s *= 0.25f;
        if (s > mx) {
            const float corr = __expf(mx - s);
            sum = sum * corr + 1.f;
            #pragma unroll
            for (int d = 0; d < 16; d++) acc[d] = acc[d] * corr + vs[m][d];
            mx = s;
        } else {
            const float e = __expf(s - mx);
            sum += e;
            #pragma unroll
            for (int d = 0; d < 16; d++) acc[d] += e * vs[m][d];
        }
    }

    const float inv = 1.f / sum;
    #pragma unroll
    for (int d = 0; d < 16; d++)
        cat[(size_t)b * 128 * HW + (size_t)(64 + h * 16 + d) * HW + p] = acc[d] * inv;
}

// ---------------- launch -----------------------------------------------------
extern "C" void kernel_launch(void* const* d_in, const int* in_sizes, int n_in,
                              void* d_out, int out_size)
{
    const float* x     = (const float*)d_in[0];
    const float* Wqkv  = (const float*)d_in[1];
    const float* bqkv  = (const float*)d_in[2];
    const float* Wdw   = (const float*)d_in[3];
    const float* bdw   = (const float*)d_in[4];
    const float* Wa1   = (const float*)d_in[5];
    const float* ba1   = (const float*)d_in[6];
    const float* Wa2   = (const float*)d_in[7];
    const float* ba2   = (const float*)d_in[8];
    const float* Wq    = (const float*)d_in[9];
    const float* bq    = (const float*)d_in[10];
    const float* Wkv   = (const float*)d_in[11];
    const float* bkv   = (const float*)d_in[12];
    const float* Wproj = (const float*)d_in[13];
    const float* bproj = (const float*)d_in[14];
    float* out = (float*)d_out;

    float *qkv, *qkvdw, *a, *cat, *qg, *xp, *kv;
    cudaGetSymbolAddress((void**)&qkv,   g_qkv);
    cudaGetSymbolAddress((void**)&qkvdw, g_qkvdw);
    cudaGetSymbolAddress((void**)&a,     g_a);
    cudaGetSymbolAddress((void**)&cat,   g_cat);
    cudaGetSymbolAddress((void**)&qg,    g_qg);
    cudaGetSymbolAddress((void**)&xp,    g_xp);
    cudaGetSymbolAddress((void**)&kv,    g_kv);

    // 1) qkv = conv1x1(x) : (B,192,HW)
    conv_gemm<0, false><<<dim3(HW / 128, 3, NB), 256>>>(
        x, 128 * HW, 0, Wqkv, bqkv, 128,
        qkv, 192 * HW, 0, nullptr, 0, 0, HW);

    // 2) depthwise 3x3
    dwconv3_kernel<<<dim3(WW / 32, HH / 8, NB * 192), dim3(32, 8)>>>(
        qkv, Wdw, bdw, qkvdw);

    // 3) a = swish(conv1x1(q*k, Wa1)) — q*k fused into the X load
    conv_gemm<1, true><<<dim3(HW / 128, 1, NB), 256>>>(
        qkvdw, 192 * HW, 64 * HW, Wa1, ba1, 64,
        a, 64 * HW, 0, nullptr, 0, 0, HW);

    // 4) res_h = tanh(conv1x1(a, Wa2)*0.25)*v  -> cat channels [0,64)
    conv_gemm<2, false><<<dim3(HW / 128, 1, NB), 256>>>(
        a, 64 * HW, 0, Wa2, ba2, 64,
        cat, 128 * HW, 0, qkvdw, 192 * HW, 128, HW);

    // 5) qg = conv1x1(x, Wq) : (B,64,HW)
    conv_gemm<0, false><<<dim3(HW / 128, 1, NB), 256>>>(
        x, 128 * HW, 0, Wq, bq, 128,
        qg, 64 * HW, 0, nullptr, 0, 0, HW);

    // 6) avgpool 8x8
    avgpool8<<<NB * 128 * 256 / 256, 256>>>(x, xp);

    // 7) kv = conv1x1(xp, Wkv) : (B,128,256)
    conv_gemm<0, false><<<dim3(256 / 128, 2, NB), 256>>>(
        xp, 128 * 256, 0, Wkv, bkv, 128,
        kv, 128 * 256, 0, nullptr, 0, 0, 256);

    // 8) low-freq attention -> cat channels [64,128)
    lowfreq_attn<<<dim3(HW / 128, 4, NB), 128>>>(qg, kv, cat);

    // 9) out = conv1x1(cat, Wproj)
    conv_gemm<0, false><<<dim3(HW / 128, 2, NB), 256>>>(
        cat, 128 * HW, 0, Wproj, bproj, 128,
        out, 128 * HW, 0, nullptr, 0, 0, HW);
}

// round 2
// speedup vs baseline: 1.0085x; 1.0085x over previous
#include <cuda_runtime.h>
#include <math.h>

#define HW   16384
#define HH   128
#define WW   128
#define NB   4

typedef unsigned long long u64;

__device__ __forceinline__ u64 pack2(float lo, float hi) {
    u64 r; asm("mov.b64 %0,{%1,%2};" : "=l"(r) : "f"(lo), "f"(hi)); return r;
}
__device__ __forceinline__ void unpack2(u64 v, float& lo, float& hi) {
    asm("mov.b64 {%0,%1},%2;" : "=f"(lo), "=f"(hi) : "l"(v));
}
__device__ __forceinline__ u64 ffma2(u64 a, u64 b, u64 c) {
    u64 r; asm("fma.rn.f32x2 %0,%1,%2,%3;" : "=l"(r) : "l"(a), "l"(b), "l"(c)); return r;
}

// ---------------- scratch (device globals; no allocations allowed) ----------
__device__ float g_qkv  [NB * 192 * HW];
__device__ float g_qkvdw[NB * 192 * HW];
__device__ float g_a    [NB * 64  * HW];
__device__ float g_cat  [NB * 128 * HW];
__device__ float g_qg   [NB * 64  * HW];
__device__ float g_xp   [NB * 128 * 256];
__device__ float g_kv   [NB * 128 * 256];

// ---------------- conv1x1 GEMM: dst[oc,p] = sum_c W[oc,c]*X[c,p] ------------
// 64 oc x 128 px tile, K-chunk 16, 256 threads, micro-tile 8 oc x 4 px.
// f32x2 packed FMA over pixel pairs; W stored duplicated (w,w) in smem.
// Double-buffered smem, single __syncthreads per K-chunk.
// EPI: 0 none, 1 swish, 2 tanh(x*0.25)*vaux. MUL: X = src * src[+src2_off].
template<int EPI, bool MUL>
__global__ void __launch_bounds__(256) conv_gemm(
    const float* __restrict__ src, int src_bstride, int src2_off,
    const float* __restrict__ Wt, const float* __restrict__ bias, int IC,
    float* __restrict__ dst, int dst_bstride, int dst_oc_base,
    const float* __restrict__ vaux, int vaux_bstride, int vaux_oc_base,
    int NPIX)
{
    const int tid = threadIdx.x;
    const int tx  = tid & 31;
    const int ty  = tid >> 5;
    const int p0  = blockIdx.x * 128;
    const int oc0 = blockIdx.y * 64;
    const int b   = blockIdx.z;

    __shared__ __align__(16) u64   Ws[2][64][16];   // packed (w,w)
    __shared__ __align__(16) float Xs[2][16][128];

    const float* srcb = src + (size_t)b * src_bstride;

    const int wkk  = tid & 15, wocl = tid >> 4;   // W loader: 4 rows of 16 oc
    const int xp   = tid & 127, xkk0 = tid >> 7;  // X loader: 8 rows of 2 kk

    u64 acc[8][2];
    #pragma unroll
    for (int i = 0; i < 8; i++) { acc[i][0] = 0ull; acc[i][1] = 0ull; }

    float wr[4], xr[8];

    // prime buffer 0
    #pragma unroll
    for (int r = 0; r < 4; r++)
        wr[r] = __ldg(&Wt[(size_t)(oc0 + wocl + r * 16) * IC + wkk]);
    #pragma unroll
    for (int r = 0; r < 8; r++) {
        const float* sp = srcb + (size_t)(xkk0 + r * 2) * NPIX + p0 + xp;
        float v = __ldg(sp);
        if (MUL) v *= __ldg(sp + src2_off);
        xr[r] = v;
    }
    #pragma unroll
    for (int r = 0; r < 4; r++) Ws[0][wocl + r * 16][wkk] = pack2(wr[r], wr[r]);
    #pragma unroll
    for (int r = 0; r < 8; r++) Xs[0][xkk0 + r * 2][xp] = xr[r];
    __syncthreads();

    const int nk = IC >> 4;
    int cur = 0;
    for (int it = 0; it < nk; it++) {
        if (it + 1 < nk) {
            const int k0 = (it + 1) << 4;
            #pragma unroll
            for (int r = 0; r < 4; r++)
                wr[r] = __ldg(&Wt[(size_t)(oc0 + wocl + r * 16) * IC + k0 + wkk]);
            #pragma unroll
            for (int r = 0; r < 8; r++) {
                const float* sp = srcb + (size_t)(k0 + xkk0 + r * 2) * NPIX + p0 + xp;
                float v = __ldg(sp);
                if (MUL) v *= __ldg(sp + src2_off);
                xr[r] = v;
            }
        }
        #pragma unroll
        for (int kk = 0; kk < 16; kk++) {
            const ulonglong2 xv =
                *reinterpret_cast<const ulonglong2*>(&Xs[cur][kk][tx * 4]);
            #pragma unroll
            for (int i = 0; i < 8; i++) {
                const u64 ww = Ws[cur][ty * 8 + i][kk];
                acc[i][0] = ffma2(ww, xv.x, acc[i][0]);
                acc[i][1] = ffma2(ww, xv.y, acc[i][1]);
            }
        }
        if (it + 1 < nk) {
            #pragma unroll
            for (int r = 0; r < 4; r++) Ws[cur ^ 1][wocl + r * 16][wkk] = pack2(wr[r], wr[r]);
            #pragma unroll
            for (int r = 0; r < 8; r++) Xs[cur ^ 1][xkk0 + r * 2][xp] = xr[r];
        }
        __syncthreads();
        cur ^= 1;
    }

    // ---- epilogue
    float* dstb = dst + (size_t)b * dst_bstride;
    const float* vb = (EPI == 2) ? (vaux + (size_t)b * vaux_bstride) : nullptr;

    #pragma unroll
    for (int i = 0; i < 8; i++) {
        const int oc = oc0 + ty * 8 + i;
        const float bv = __ldg(&bias[oc]);
        float* drow = dstb + (size_t)(dst_oc_base + oc) * NPIX + p0 + tx * 4;
        float v[4];
        unpack2(acc[i][0], v[0], v[1]);
        unpack2(acc[i][1], v[2], v[3]);
        #pragma unroll
        for (int j = 0; j < 4; j++) v[j] += bv;
        if (EPI == 1) {
            #pragma unroll
            for (int j = 0; j < 4; j++) v[j] = v[j] / (1.f + __expf(-v[j]));
        } else if (EPI == 2) {
            const float* vrow = vb + (size_t)(vaux_oc_base + oc) * NPIX + p0 + tx * 4;
            #pragma unroll
            for (int j = 0; j < 4; j++) v[j] = tanhf(v[j] * 0.25f) * __ldg(&vrow[j]);
        }
        float4 o; o.x = v[0]; o.y = v[1]; o.z = v[2]; o.w = v[3];
        *reinterpret_cast<float4*>(drow) = o;
    }
}

// ---------------- depthwise 3x3 SAME (zero pad) -----------------------------
__global__ void dwconv3_kernel(const float* __restrict__ src,
                               const float* __restrict__ w,
                               const float* __restrict__ bias,
                               float* __restrict__ dst)
{
    const int plane = blockIdx.z;            // b*192 + c
    const int c = plane % 192;
    const int x = blockIdx.x * 32 + threadIdx.x;
    const int y = blockIdx.y * 8 + threadIdx.y;
    const float* sp = src + (size_t)plane * HW;

    float wk[9];
    #pragma unroll
    for (int i = 0; i < 9; i++) wk[i] = __ldg(&w[c * 9 + i]);

    float s = __ldg(&bias[c]);
    #pragma unroll
    for (int dy = -1; dy <= 1; dy++) {
        const int yy = y + dy;
        if (yy < 0 || yy >= HH) continue;
        #pragma unroll
        for (int dx = -1; dx <= 1; dx++) {
            const int xx = x + dx;
            if (xx < 0 || xx >= WW) continue;
            s += wk[(dy + 1) * 3 + (dx + 1)] * __ldg(&sp[yy * WW + xx]);
        }
    }
    dst[(size_t)plane * HW + y * WW + x] = s;
}

// ---------------- 8x8 avgpool: (B,128,128,128) -> (B,128,16,16) -------------
__global__ void avgpool8(const float* __restrict__ x, float* __restrict__ xp)
{
    const int idx = blockIdx.x * 256 + threadIdx.x;
    const int pos = idx & 255;
    const int j = pos & 15, i = pos >> 4;
    const int bc = idx >> 8;
    const float* sp = x + (size_t)bc * HW + (i * 8) * WW + j * 8;
    float s = 0.f;
    #pragma unroll
    for (int r = 0; r < 8; r++) {
        const float4 a = *reinterpret_cast<const float4*>(sp + r * WW);
        const float4 b = *reinterpret_cast<const float4*>(sp + r * WW + 4);
        s += a.x + a.y + a.z + a.w + b.x + b.y + b.z + b.w;
    }
    xp[idx] = s * (1.f / 64.f);
}

// ---------------- low-freq softmax attention (f32x2 over head-dim pairs) ----
__global__ void __launch_bounds__(128) lowfreq_attn(
    const float* __restrict__ qg, const float* __restrict__ kv,
    float* __restrict__ cat)
{
    const int b = blockIdx.z, h = blockIdx.y;
    const int p = blockIdx.x * 128 + threadIdx.x;

    __shared__ __align__(16) u64 ks2[256][8];
    __shared__ __align__(16) u64 vs2[256][8];

    const float* kvb = kv + (size_t)b * 128 * 256;
    for (int i = threadIdx.x; i < 2048; i += 128) {
        const int d2 = i >> 8, m = i & 255;
        ks2[m][d2] = pack2(kvb[(h * 16 + 2 * d2) * 256 + m],
                           kvb[(h * 16 + 2 * d2 + 1) * 256 + m]);
        vs2[m][d2] = pack2(kvb[(64 + h * 16 + 2 * d2) * 256 + m],
                           kvb[(64 + h * 16 + 2 * d2 + 1) * 256 + m]);
    }
    __syncthreads();

    u64 q2[8];
    #pragma unroll
    for (int d2 = 0; d2 < 8; d2++) {
        const size_t base = (size_t)b * 64 * HW + (size_t)(h * 16 + 2 * d2) * HW + p;
        q2[d2] = pack2(0.25f * __ldg(&qg[base]), 0.25f * __ldg(&qg[base + HW]));
    }

    float mx = -1e30f, sum = 0.f;
    u64 acc2[8];
    #pragma unroll
    for (int d2 = 0; d2 < 8; d2++) acc2[d2] = 0ull;

    for (int m = 0; m < 256; m++) {
        u64 s2 = 0ull;
        #pragma unroll
        for (int d2 = 0; d2 < 8; d2++) s2 = ffma2(q2[d2], ks2[m][d2], s2);
        float slo, shi; unpack2(s2, slo, shi);
        const float s = slo + shi;
        if (s > mx) {
            const float corr = __expf(mx - s);
            const u64 c2 = pack2(corr, corr);
            sum = sum * corr + 1.f;
            #pragma unroll
            for (int d2 = 0; d2 < 8; d2++) acc2[d2] = ffma2(acc2[d2], c2, vs2[m][d2]);
            mx = s;
        } else {
            const float e = __expf(s - mx);
            const u64 e2 = pack2(e, e);
            sum += e;
            #pragma unroll
            for (int d2 = 0; d2 < 8; d2++) acc2[d2] = ffma2(e2, vs2[m][d2], acc2[d2]);
        }
    }

    const float inv = 1.f / sum;
    #pragma unroll
    for (int d2 = 0; d2 < 8; d2++) {
        float lo, hi; unpack2(acc2[d2], lo, hi);
        const size_t base = (size_t)b * 128 * HW + (size_t)(64 + h * 16 + 2 * d2) * HW + p;
        cat[base]      = lo * inv;
        cat[base + HW] = hi * inv;
    }
}

// ---------------- launch -----------------------------------------------------
extern "C" void kernel_launch(void* const* d_in, const int* in_sizes, int n_in,
                              void* d_out, int out_size)
{
    const float* x     = (const float*)d_in[0];
    const float* Wqkv  = (const float*)d_in[1];
    const float* bqkv  = (const float*)d_in[2];
    const float* Wdw   = (const float*)d_in[3];
    const float* bdw   = (const float*)d_in[4];
    const float* Wa1   = (const float*)d_in[5];
    const float* ba1   = (const float*)d_in[6];
    const float* Wa2   = (const float*)d_in[7];
    const float* ba2   = (const float*)d_in[8];
    const float* Wq    = (const float*)d_in[9];
    const float* bq    = (const float*)d_in[10];
    const float* Wkv   = (const float*)d_in[11];
    const float* bkv   = (const float*)d_in[12];
    const float* Wproj = (const float*)d_in[13];
    const float* bproj = (const float*)d_in[14];
    float* out = (float*)d_out;

    float *qkv, *qkvdw, *a, *cat, *qg, *xp, *kv;
    cudaGetSymbolAddress((void**)&qkv,   g_qkv);
    cudaGetSymbolAddress((void**)&qkvdw, g_qkvdw);
    cudaGetSymbolAddress((void**)&a,     g_a);
    cudaGetSymbolAddress((void**)&cat,   g_cat);
    cudaGetSymbolAddress((void**)&qg,    g_qg);
    cudaGetSymbolAddress((void**)&xp,    g_xp);
    cudaGetSymbolAddress((void**)&kv,    g_kv);

    // 1) qkv = conv1x1(x) : (B,192,HW)
    conv_gemm<0, false><<<dim3(HW / 128, 3, NB), 256>>>(
        x, 128 * HW, 0, Wqkv, bqkv, 128,
        qkv, 192 * HW, 0, nullptr, 0, 0, HW);

    // 2) depthwise 3x3
    dwconv3_kernel<<<dim3(WW / 32, HH / 8, NB * 192), dim3(32, 8)>>>(
        qkv, Wdw, bdw, qkvdw);

    // 3) a = swish(conv1x1(q*k, Wa1))
    conv_gemm<1, true><<<dim3(HW / 128, 1, NB), 256>>>(
        qkvdw, 192 * HW, 64 * HW, Wa1, ba1, 64,
        a, 64 * HW, 0, nullptr, 0, 0, HW);

    // 4) res_h = tanh(conv1x1(a, Wa2)*0.25)*v -> cat channels [0,64)
    conv_gemm<2, false><<<dim3(HW / 128, 1, NB), 256>>>(
        a, 64 * HW, 0, Wa2, ba2, 64,
        cat, 128 * HW, 0, qkvdw, 192 * HW, 128, HW);

    // 5) qg = conv1x1(x, Wq) : (B,64,HW)
    conv_gemm<0, false><<<dim3(HW / 128, 1, NB), 256>>>(
        x, 128 * HW, 0, Wq, bq, 128,
        qg, 64 * HW, 0, nullptr, 0, 0, HW);

    // 6) avgpool 8x8
    avgpool8<<<NB * 128 * 256 / 256, 256>>>(x, xp);

    // 7) kv = conv1x1(xp, Wkv) : (B,128,256)
    conv_gemm<0, false><<<dim3(256 / 128, 2, NB), 256>>>(
        xp, 128 * 256, 0, Wkv, bkv, 128,
        kv, 128 * 256, 0, nullptr, 0, 0, 256);

    // 8) low-freq attention -> cat channels [64,128)
    lowfreq_attn<<<dim3(HW / 128, 4, NB), 128>>>(qg, kv, cat);

    // 9) out = conv1x1(cat, Wproj)
    conv_gemm<0, false><<<dim3(HW / 128, 2, NB), 256>>>(
        cat, 128 * HW, 0, Wproj, bproj, 128,
        out, 128 * HW, 0, nullptr, 0, 0, HW);
}

// round 4
// speedup vs baseline: 1.3283x; 1.3171x over previous
#include <cuda_runtime.h>
#include <cuda_bf16.h>
#include <math.h>

#define HW   16384
#define HH   128
#define WW   128
#define NB   4

typedef unsigned long long u64;
typedef unsigned int u32;

// ---------------- f32x2 helpers (attention) ---------------------------------
__device__ __forceinline__ u64 pack2(float lo, float hi) {
    u64 r; asm("mov.b64 %0,{%1,%2};" : "=l"(r) : "f"(lo), "f"(hi)); return r;
}
__device__ __forceinline__ void unpack2(u64 v, float& lo, float& hi) {
    asm("mov.b64 {%0,%1},%2;" : "=f"(lo), "=f"(hi) : "l"(v));
}
__device__ __forceinline__ u64 ffma2(u64 a, u64 b, u64 c) {
    u64 r; asm("fma.rn.f32x2 %0,%1,%2,%3;" : "=l"(r) : "l"(a), "l"(b), "l"(c)); return r;
}

// ---------------- scratch ----------------------------------------------------
__device__ float g_qkv  [NB * 192 * HW];
__device__ float g_qkvdw[NB * 192 * HW];
__device__ float g_a    [NB * 64  * HW];
__device__ float g_cat  [NB * 128 * HW];
__device__ float g_qg   [NB * 64  * HW];
__device__ float g_xp   [NB * 128 * 256];
__device__ float g_kv   [NB * 128 * 256];

// ---------------- mma helpers ------------------------------------------------
__device__ __forceinline__ u32 smem_u32(const void* p) {
    u32 a;
    asm("{ .reg .u64 t; cvta.to.shared.u64 t, %1; cvt.u32.u64 %0, t; }"
        : "=r"(a) : "l"(p));
    return a;
}
__device__ __forceinline__ void ldm_x4(u32 a, u32& r0, u32& r1, u32& r2, u32& r3) {
    asm volatile("ldmatrix.sync.aligned.m8n8.x4.shared.b16 {%0,%1,%2,%3},[%4];"
                 : "=r"(r0), "=r"(r1), "=r"(r2), "=r"(r3) : "r"(a));
}
__device__ __forceinline__ void ldm_x4t(u32 a, u32& r0, u32& r1, u32& r2, u32& r3) {
    asm volatile("ldmatrix.sync.aligned.m8n8.x4.trans.shared.b16 {%0,%1,%2,%3},[%4];"
                 : "=r"(r0), "=r"(r1), "=r"(r2), "=r"(r3) : "r"(a));
}
__device__ __forceinline__ void mma_bf16(float* c, const u32* a, u32 b0, u32 b1) {
    asm volatile(
        "mma.sync.aligned.m16n8k16.row.col.f32.bf16.bf16.f32 "
        "{%0,%1,%2,%3},{%4,%5,%6,%7},{%8,%9},{%0,%1,%2,%3};"
        : "+f"(c[0]), "+f"(c[1]), "+f"(c[2]), "+f"(c[3])
        : "r"(a[0]), "r"(a[1]), "r"(a[2]), "r"(a[3]), "r"(b0), "r"(b1));
}

// split x into hi(bf16) + lo(bf16 of residual); pack pairs (x0 low, x1 high)
__device__ __forceinline__ void split2(float x0, float x1, u32& h, u32& l) {
    __nv_bfloat16 h0 = __float2bfloat16(x0);
    __nv_bfloat16 h1 = __float2bfloat16(x1);
    float r0 = x0 - __bfloat162float(h0);
    float r1 = x1 - __bfloat162float(h1);
    __nv_bfloat162 hp; hp.x = h0; hp.y = h1;
    __nv_bfloat162 lp; lp.x = __float2bfloat16(r0); lp.y = __float2bfloat16(r1);
    h = *reinterpret_cast<u32*>(&hp);
    l = *reinterpret_cast<u32*>(&lp);
}

#define APITCH 24    // bf16 elems per A row (16 data + 8 pad), 48B
#define BPITCH 136   // bf16 elems per B row (128 data + 8 pad), 272B

__device__ __forceinline__ void store8(__nv_bfloat16* hdst, __nv_bfloat16* ldst,
                                       const float* v) {
    u32 hp[4], lp[4];
    #pragma unroll
    for (int j = 0; j < 4; j++) split2(v[2 * j], v[2 * j + 1], hp[j], lp[j]);
    *reinterpret_cast<uint4*>(hdst) = make_uint4(hp[0], hp[1], hp[2], hp[3]);
    *reinterpret_cast<uint4*>(ldst) = make_uint4(lp[0], lp[1], lp[2], lp[3]);
}

// ---------------- bf16-split tensor-core conv1x1 GEMM -----------------------
// D[oc,p] = sum_c W[oc,c]*X[c,p].  Block 128 oc x 128 px, 8 warps (64x32 each),
// K-chunk 16, double-buffered smem.  2-term bf16 split, 3 cross products.
// EPI: 0 none, 1 swish, 2 tanh(x*0.25)*vaux.  MUL: X = src*src[+src2_off].
template<int EPI, bool MUL>
__global__ void __launch_bounds__(256, 2) conv_gemm_mma(
    const float* __restrict__ src, int src_bstride, int src2_off,
    const float* __restrict__ Wt, const float* __restrict__ bias, int IC, int OC,
    float* __restrict__ dst, int dst_bstride, int dst_oc_base,
    const float* __restrict__ vaux, int vaux_bstride, int vaux_oc_base,
    int NPIX)
{
    __shared__ __align__(16) __nv_bfloat16 Ah[2][128 * APITCH];
    __shared__ __align__(16) __nv_bfloat16 Al[2][128 * APITCH];
    __shared__ __align__(16) __nv_bfloat16 Bh[2][16 * BPITCH];
    __shared__ __align__(16) __nv_bfloat16 Bl[2][16 * BPITCH];

    const int tid  = threadIdx.x;
    const int lane = tid & 31, warp = tid >> 5;
    const int wm = warp & 1, wn = warp >> 1;      // warp grid 2(m) x 4(n)
    const int p0  = blockIdx.x * 128;
    const int oc0 = blockIdx.y * 128;
    const int b   = blockIdx.z;

    // loader indices
    const int arow = tid >> 1, akb = (tid & 1) * 8;
    const bool arow_ok = (oc0 + arow) < OC;
    const float* wrow = Wt + (size_t)(oc0 + arow) * IC + akb;
    const int bk = tid >> 4, bp = (tid & 15) * 8;
    const float* srcb = src + (size_t)b * src_bstride + p0 + bp;

    const int nk = IC >> 4;

    float c[4][4][4];
    #pragma unroll
    for (int i = 0; i < 4; i++)
        #pragma unroll
        for (int j = 0; j < 4; j++)
            #pragma unroll
            for (int q = 0; q < 4; q++) c[i][j][q] = 0.f;

    float arx[8], brx[8];
    // ---- prime chunk 0
    if (arow_ok) {
        float4 t0 = *(const float4*)(wrow);
        float4 t1 = *(const float4*)(wrow + 4);
        arx[0]=t0.x; arx[1]=t0.y; arx[2]=t0.z; arx[3]=t0.w;
        arx[4]=t1.x; arx[5]=t1.y; arx[6]=t1.z; arx[7]=t1.w;
    } else {
        #pragma unroll
        for (int i = 0; i < 8; i++) arx[i] = 0.f;
    }
    {
        const float* srow = srcb + (size_t)bk * NPIX;
        float4 t0 = *(const float4*)srow;
        float4 t1 = *(const float4*)(srow + 4);
        if (MUL) {
            float4 m0 = *(const float4*)(srow + src2_off);
            float4 m1 = *(const float4*)(srow + src2_off + 4);
            t0.x*=m0.x; t0.y*=m0.y; t0.z*=m0.z; t0.w*=m0.w;
            t1.x*=m1.x; t1.y*=m1.y; t1.z*=m1.z; t1.w*=m1.w;
        }
        brx[0]=t0.x; brx[1]=t0.y; brx[2]=t0.z; brx[3]=t0.w;
        brx[4]=t1.x; brx[5]=t1.y; brx[6]=t1.z; brx[7]=t1.w;
    }
    store8(&Ah[0][arow * APITCH + akb], &Al[0][arow * APITCH + akb], arx);
    store8(&Bh[0][bk * BPITCH + bp],   &Bl[0][bk * BPITCH + bp],   brx);
    __syncthreads();

    // per-lane ldmatrix address parts
    const int grp = lane >> 3, lr = lane & 7;
    const int r8  = (grp & 1) * 8 + lr;
    const int kh8 = (grp >> 1) * 8;
    const u32 Ah0 = smem_u32(Ah), Al0 = smem_u32(Al);
    const u32 Bh0 = smem_u32(Bh), Bl0 = smem_u32(Bl);
    const u32 aoffs = ((u32)(wm * 64 + r8) * APITCH + kh8) * 2;
    const u32 boffs = ((u32)r8 * BPITCH + wn * 32 + kh8) * 2;
    const u32 ABUF = 128 * APITCH * 2;
    const u32 BBUF = 16 * BPITCH * 2;

    int cur = 0;
    for (int it = 0; it < nk; it++) {
        const bool more = (it + 1) < nk;
        if (more) {
            const int k0 = (it + 1) << 4;
            if (arow_ok) {
                float4 t0 = *(const float4*)(wrow + k0);
                float4 t1 = *(const float4*)(wrow + k0 + 4);
                arx[0]=t0.x; arx[1]=t0.y; arx[2]=t0.z; arx[3]=t0.w;
                arx[4]=t1.x; arx[5]=t1.y; arx[6]=t1.z; arx[7]=t1.w;
            }
            const float* srow = srcb + (size_t)(k0 + bk) * NPIX;
            float4 t0 = *(const float4*)srow;
            float4 t1 = *(const float4*)(srow + 4);
            if (MUL) {
                float4 m0 = *(const float4*)(srow + src2_off);
                float4 m1 = *(const float4*)(srow + src2_off + 4);
                t0.x*=m0.x; t0.y*=m0.y; t0.z*=m0.z; t0.w*=m0.w;
                t1.x*=m1.x; t1.y*=m1.y; t1.z*=m1.z; t1.w*=m1.w;
            }
            brx[0]=t0.x; brx[1]=t0.y; brx[2]=t0.z; brx[3]=t0.w;
            brx[4]=t1.x; brx[5]=t1.y; brx[6]=t1.z; brx[7]=t1.w;
        }

        // ---- compute on buffer cur
        const u32 ab = Ah0 + cur * ABUF, al0 = Al0 + cur * ABUF;
        const u32 bb = Bh0 + cur * BBUF, bl0 = Bl0 + cur * BBUF;
        u32 bh[2][4], bl[2][4];
        #pragma unroll
        for (int g = 0; g < 2; g++) {
            ldm_x4t(bb  + boffs + g * 32, bh[g][0], bh[g][1], bh[g][2], bh[g][3]);
            ldm_x4t(bl0 + boffs + g * 32, bl[g][0], bl[g][1], bl[g][2], bl[g][3]);
        }
        #pragma unroll
        for (int mi = 0; mi < 4; mi++) {
            u32 ah[4], alr[4];
            ldm_x4(ab  + aoffs + mi * (16 * APITCH * 2), ah[0], ah[1], ah[2], ah[3]);
            ldm_x4(al0 + aoffs + mi * (16 * APITCH * 2), alr[0], alr[1], alr[2], alr[3]);
            #pragma unroll
            for (int nj = 0; nj < 4; nj++) {
                const int g = nj >> 1, s = nj & 1;
                mma_bf16(c[mi][nj], ah,  bh[g][2*s], bh[g][2*s+1]);
                mma_bf16(c[mi][nj], ah,  bl[g][2*s], bl[g][2*s+1]);
                mma_bf16(c[mi][nj], alr, bh[g][2*s], bh[g][2*s+1]);
            }
        }

        if (more) {
            store8(&Ah[cur ^ 1][arow * APITCH + akb], &Al[cur ^ 1][arow * APITCH + akb], arx);
            store8(&Bh[cur ^ 1][bk * BPITCH + bp],   &Bl[cur ^ 1][bk * BPITCH + bp],   brx);
        }
        __syncthreads();
        cur ^= 1;
    }

    // ---- epilogue
    const int r0 = lane >> 2;
    const int cp = (lane & 3) * 2;
    float* dstb = dst + (size_t)b * dst_bstride;
    const float* vb = (EPI == 2) ? (vaux + (size_t)b * vaux_bstride) : nullptr;

    #pragma unroll
    for (int mi = 0; mi < 4; mi++) {
        #pragma unroll
        for (int half = 0; half < 2; half++) {
            const int oc = oc0 + wm * 64 + mi * 16 + half * 8 + r0;
            if (oc < OC) {
                const float bv = bias[oc];
                float* drow = dstb + (size_t)(dst_oc_base + oc) * NPIX + p0 + wn * 32 + cp;
                const float* vrow = (EPI == 2)
                    ? vb + (size_t)(vaux_oc_base + oc) * NPIX + p0 + wn * 32 + cp : nullptr;
                #pragma unroll
                for (int nj = 0; nj < 4; nj++) {
                    float v0 = c[mi][nj][half * 2]     + bv;
                    float v1 = c[mi][nj][half * 2 + 1] + bv;
                    if (EPI == 1) {
                        v0 = v0 / (1.f + __expf(-v0));
                        v1 = v1 / (1.f + __expf(-v1));
                    } else if (EPI == 2) {
                        v0 = tanhf(v0 * 0.25f) * __ldg(&vrow[nj * 8]);
                        v1 = tanhf(v1 * 0.25f) * __ldg(&vrow[nj * 8 + 1]);
                    }
                    float2 o; o.x = v0; o.y = v1;
                    *reinterpret_cast<float2*>(drow + nj * 8) = o;
                }
            }
        }
    }
}

// ---------------- depthwise 3x3 SAME ----------------------------------------
__global__ void dwconv3_kernel(const float* __restrict__ src,
                               const float* __restrict__ w,
                               const float* __restrict__ bias,
                               float* __restrict__ dst)
{
    const int plane = blockIdx.z;
    const int c = plane % 192;
    const int x = blockIdx.x * 32 + threadIdx.x;
    const int y = blockIdx.y * 8 + threadIdx.y;
    const float* sp = src + (size_t)plane * HW;

    float wk[9];
    #pragma unroll
    for (int i = 0; i < 9; i++) wk[i] = __ldg(&w[c * 9 + i]);

    float s = __ldg(&bias[c]);
    #pragma unroll
    for (int dy = -1; dy <= 1; dy++) {
        const int yy = y + dy;
        if (yy < 0 || yy >= HH) continue;
        #pragma unroll
        for (int dx = -1; dx <= 1; dx++) {
            const int xx = x + dx;
            if (xx < 0 || xx >= WW) continue;
            s += wk[(dy + 1) * 3 + (dx + 1)] * __ldg(&sp[yy * WW + xx]);
        }
    }
    dst[(size_t)plane * HW + y * WW + x] = s;
}

// ---------------- 8x8 avgpool ------------------------------------------------
__global__ void avgpool8(const float* __restrict__ x, float* __restrict__ xp)
{
    const int idx = blockIdx.x * 256 + threadIdx.x;
    const int pos = idx & 255;
    const int j = pos & 15, i = pos >> 4;
    const int bc = idx >> 8;
    const float* sp = x + (size_t)bc * HW + (i * 8) * WW + j * 8;
    float s = 0.f;
    #pragma unroll
    for (int r = 0; r < 8; r++) {
        const float4 a = *reinterpret_cast<const float4*>(sp + r * WW);
        const float4 b = *reinterpret_cast<const float4*>(sp + r * WW + 4);
        s += a.x + a.y + a.z + a.w + b.x + b.y + b.z + b.w;
    }
    xp[idx] = s * (1.f / 64.f);
}

// ---------------- low-freq softmax attention --------------------------------
__global__ void __launch_bounds__(128) lowfreq_attn(
    const float* __restrict__ qg, const float* __restrict__ kv,
    float* __restrict__ cat)
{
    const int b = blockIdx.z, h = blockIdx.y;
    const int p = blockIdx.x * 128 + threadIdx.x;

    __shared__ __align__(16) u64 ks2[256][8];
    __shared__ __align__(16) u64 vs2[256][8];

    const float* kvb = kv + (size_t)b * 128 * 256;
    for (int i = threadIdx.x; i < 2048; i += 128) {
        const int d2 = i >> 8, m = i & 255;
        ks2[m][d2] = pack2(kvb[(h * 16 + 2 * d2) * 256 + m],
                           kvb[(h * 16 + 2 * d2 + 1) * 256 + m]);
        vs2[m][d2] = pack2(kvb[(64 + h * 16 + 2 * d2) * 256 + m],
                           kvb[(64 + h * 16 + 2 * d2 + 1) * 256 + m]);
    }
    __syncthreads();

    u64 q2[8];
    #pragma unroll
    for (int d2 = 0; d2 < 8; d2++) {
        const size_t base = (size_t)b * 64 * HW + (size_t)(h * 16 + 2 * d2) * HW + p;
        q2[d2] = pack2(0.25f * __ldg(&qg[base]), 0.25f * __ldg(&qg[base + HW]));
    }

    float mx = -1e30f, sum = 0.f;
    u64 acc2[8];
    #pragma unroll
    for (int d2 = 0; d2 < 8; d2++) acc2[d2] = 0ull;

    for (int m = 0; m < 256; m++) {
        u64 s2 = 0ull;
        #pragma unroll
        for (int d2 = 0; d2 < 8; d2++) s2 = ffma2(q2[d2], ks2[m][d2], s2);
        float slo, shi; unpack2(s2, slo, shi);
        const float s = slo + shi;
        if (s > mx) {
            const float corr = __expf(mx - s);
            const u64 c2 = pack2(corr, corr);
            sum = sum * corr + 1.f;
            #pragma unroll
            for (int d2 = 0; d2 < 8; d2++) acc2[d2] = ffma2(acc2[d2], c2, vs2[m][d2]);
            mx = s;
        } else {
            const float e = __expf(s - mx);
            const u64 e2 = pack2(e, e);
            sum += e;
            #pragma unroll
            for (int d2 = 0; d2 < 8; d2++) acc2[d2] = ffma2(e2, vs2[m][d2], acc2[d2]);
        }
    }

    const float inv = 1.f / sum;
    #pragma unroll
    for (int d2 = 0; d2 < 8; d2++) {
        float lo, hi; unpack2(acc2[d2], lo, hi);
        const size_t base = (size_t)b * 128 * HW + (size_t)(64 + h * 16 + 2 * d2) * HW + p;
        cat[base]      = lo * inv;
        cat[base + HW] = hi * inv;
    }
}

// ---------------- launch -----------------------------------------------------
extern "C" void kernel_launch(void* const* d_in, const int* in_sizes, int n_in,
                              void* d_out, int out_size)
{
    const float* x     = (const float*)d_in[0];
    const float* Wqkv  = (const float*)d_in[1];
    const float* bqkv  = (const float*)d_in[2];
    const float* Wdw   = (const float*)d_in[3];
    const float* bdw   = (const float*)d_in[4];
    const float* Wa1   = (const float*)d_in[5];
    const float* ba1   = (const float*)d_in[6];
    const float* Wa2   = (const float*)d_in[7];
    const float* ba2   = (const float*)d_in[8];
    const float* Wq    = (const float*)d_in[9];
    const float* bq    = (const float*)d_in[10];
    const float* Wkv   = (const float*)d_in[11];
    const float* bkv   = (const float*)d_in[12];
    const float* Wproj = (const float*)d_in[13];
    const float* bproj = (const float*)d_in[14];
    float* out = (float*)d_out;

    float *qkv, *qkvdw, *a, *cat, *qg, *xp, *kv;
    cudaGetSymbolAddress((void**)&qkv,   g_qkv);
    cudaGetSymbolAddress((void**)&qkvdw, g_qkvdw);
    cudaGetSymbolAddress((void**)&a,     g_a);
    cudaGetSymbolAddress((void**)&cat,   g_cat);
    cudaGetSymbolAddress((void**)&qg,    g_qg);
    cudaGetSymbolAddress((void**)&xp,    g_xp);
    cudaGetSymbolAddress((void**)&kv,    g_kv);

    // 1) qkv = conv1x1(x) : (B,192,HW), 2 M-tiles
    conv_gemm_mma<0, false><<<dim3(HW / 128, 2, NB), 256>>>(
        x, 128 * HW, 0, Wqkv, bqkv, 128, 192,
        qkv, 192 * HW, 0, nullptr, 0, 0, HW);

    // 2) depthwise 3x3
    dwconv3_kernel<<<dim3(WW / 32, HH / 8, NB * 192), dim3(32, 8)>>>(
        qkv, Wdw, bdw, qkvdw);

    // 3) a = swish(conv1x1(q*k, Wa1))
    conv_gemm_mma<1, true><<<dim3(HW / 128, 1, NB), 256>>>(
        qkvdw, 192 * HW, 64 * HW, Wa1, ba1, 64, 64,
        a, 64 * HW, 0, nullptr, 0, 0, HW);

    // 4) res_h = tanh(conv1x1(a, Wa2)*0.25)*v -> cat channels [0,64)
    conv_gemm_mma<2, false><<<dim3(HW / 128, 1, NB), 256>>>(
        a, 64 * HW, 0, Wa2, ba2, 64, 64,
        cat, 128 * HW, 0, qkvdw, 192 * HW, 128, HW);

    // 5) qg = conv1x1(x, Wq) : (B,64,HW)
    conv_gemm_mma<0, false><<<dim3(HW / 128, 1, NB), 256>>>(
        x, 128 * HW, 0, Wq, bq, 128, 64,
        qg, 64 * HW, 0, nullptr, 0, 0, HW);

    // 6) avgpool 8x8
    avgpool8<<<NB * 128 * 256 / 256, 256>>>(x, xp);

    // 7) kv = conv1x1(xp, Wkv) : (B,128,256)
    conv_gemm_mma<0, false><<<dim3(2, 1, NB), 256>>>(
        xp, 128 * 256, 0, Wkv, bkv, 128, 128,
        kv, 128 * 256, 0, nullptr, 0, 0, 256);

    // 8) low-freq attention -> cat channels [64,128)
    lowfreq_attn<<<dim3(HW / 128, 4, NB), 128>>>(qg, kv, cat);

    // 9) out = conv1x1(cat, Wproj)
    conv_gemm_mma<0, false><<<dim3(HW / 128, 1, NB), 256>>>(
        cat, 128 * HW, 0, Wproj, bproj, 128, 128,
        out, 128 * HW, 0, nullptr, 0, 0, HW);
}

// round 5
// speedup vs baseline: 1.4437x; 1.0869x over previous
#include <cuda_runtime.h>
#include <cuda_bf16.h>
#include <math.h>

#define HW 16384
#define HH 128
#define WW 128
#define NB 4

typedef unsigned long long u64;
typedef unsigned int u32;
typedef __nv_bfloat16 bf16;

// ---------------- f32x2 helpers (attention) ---------------------------------
__device__ __forceinline__ u64 pack2(float lo, float hi) {
    u64 r; asm("mov.b64 %0,{%1,%2};" : "=l"(r) : "f"(lo), "f"(hi)); return r;
}
__device__ __forceinline__ void unpack2(u64 v, float& lo, float& hi) {
    asm("mov.b64 {%0,%1},%2;" : "=f"(lo), "=f"(hi) : "l"(v));
}
__device__ __forceinline__ u64 ffma2(u64 a, u64 b, u64 c) {
    u64 r; asm("fma.rn.f32x2 %0,%1,%2,%3;" : "=l"(r) : "l"(a), "l"(b), "l"(c)); return r;
}

// ---------------- scratch ----------------------------------------------------
__device__ __align__(256) float g_qkv [NB * 192 * HW];
__device__ __align__(256) float g_v   [NB * 64  * HW];
__device__ __align__(256) float g_qg  [NB * 64  * HW];
__device__ __align__(256) float g_kv  [NB * 128 * 256];
__device__ __align__(256) bf16  g_xh  [NB * 128 * HW];
__device__ __align__(256) bf16  g_xl  [NB * 128 * HW];
__device__ __align__(256) bf16  g_qkh [NB * 64 * HW];
__device__ __align__(256) bf16  g_qkl [NB * 64 * HW];
__device__ __align__(256) bf16  g_ah  [NB * 64 * HW];
__device__ __align__(256) bf16  g_al  [NB * 64 * HW];
__device__ __align__(256) bf16  g_ch  [NB * 128 * HW];
__device__ __align__(256) bf16  g_cl  [NB * 128 * HW];
__device__ __align__(256) bf16  g_xph [NB * 128 * 256];
__device__ __align__(256) bf16  g_xpl [NB * 128 * 256];
__device__ __align__(256) bf16  g_w1h [256 * 128];
__device__ __align__(256) bf16  g_w1l [256 * 128];
__device__ __align__(256) bf16  g_wa1h[64 * 64];
__device__ __align__(256) bf16  g_wa1l[64 * 64];
__device__ __align__(256) bf16  g_wa2h[64 * 64];
__device__ __align__(256) bf16  g_wa2l[64 * 64];
__device__ __align__(256) bf16  g_wkvh[128 * 128];
__device__ __align__(256) bf16  g_wkvl[128 * 128];
__device__ __align__(256) bf16  g_wph [128 * 128];
__device__ __align__(256) bf16  g_wpl [128 * 128];
__device__ __align__(256) float g_b1  [256];

// ---------------- mma / cp.async helpers ------------------------------------
__device__ __forceinline__ u32 smem_u32(const void* p) {
    u32 a;
    asm("{ .reg .u64 t; cvta.to.shared.u64 t, %1; cvt.u32.u64 %0, t; }"
        : "=r"(a) : "l"(p));
    return a;
}
__device__ __forceinline__ void ldm_x4(u32 a, u32& r0, u32& r1, u32& r2, u32& r3) {
    asm volatile("ldmatrix.sync.aligned.m8n8.x4.shared.b16 {%0,%1,%2,%3},[%4];"
                 : "=r"(r0), "=r"(r1), "=r"(r2), "=r"(r3) : "r"(a));
}
__device__ __forceinline__ void ldm_x4t(u32 a, u32& r0, u32& r1, u32& r2, u32& r3) {
    asm volatile("ldmatrix.sync.aligned.m8n8.x4.trans.shared.b16 {%0,%1,%2,%3},[%4];"
                 : "=r"(r0), "=r"(r1), "=r"(r2), "=r"(r3) : "r"(a));
}
__device__ __forceinline__ void mma_bf16(float* c, const u32* a, u32 b0, u32 b1) {
    asm volatile(
        "mma.sync.aligned.m16n8k16.row.col.f32.bf16.bf16.f32 "
        "{%0,%1,%2,%3},{%4,%5,%6,%7},{%8,%9},{%0,%1,%2,%3};"
        : "+f"(c[0]), "+f"(c[1]), "+f"(c[2]), "+f"(c[3])
        : "r"(a[0]), "r"(a[1]), "r"(a[2]), "r"(a[3]), "r"(b0), "r"(b1));
}
__device__ __forceinline__ void cpa16(u32 d, const void* s) {
    asm volatile("cp.async.cg.shared.global [%0],[%1],16;" :: "r"(d), "l"(s));
}
__device__ __forceinline__ void cp_commit() {
    asm volatile("cp.async.commit_group;" ::: "memory");
}
template<int N> __device__ __forceinline__ void cp_wait() {
    asm volatile("cp.async.wait_group %0;" :: "n"(N) : "memory");
}
__device__ __forceinline__ void split2(float x0, float x1, u32& h, u32& l) {
    bf16 h0 = __float2bfloat16(x0);
    bf16 h1 = __float2bfloat16(x1);
    float r0 = x0 - __bfloat162float(h0);
    float r1 = x1 - __bfloat162float(h1);
    __nv_bfloat162 hp; hp.x = h0; hp.y = h1;
    __nv_bfloat162 lp; lp.x = __float2bfloat16(r0); lp.y = __float2bfloat16(r1);
    h = *reinterpret_cast<u32*>(&hp);
    l = *reinterpret_cast<u32*>(&lp);
}
__device__ __forceinline__ void split1(float x, bf16* hd, bf16* ld, size_t o) {
    bf16 h = __float2bfloat16(x);
    hd[o] = h;
    ld[o] = __float2bfloat16(x - __bfloat162float(h));
}

// ---------------- GEMM geometry ----------------------------------------------
#define APITCH 40                 // 32 + 8 bf16
#define BPITCH 264                // 256 + 8 bf16
#define APB (64 * APITCH * 2)     // bytes per A plane per stage
#define BPB (32 * BPITCH * 2)     // bytes per B plane per stage
#define SMEM_BYTES (4 * APB + 4 * BPB)

// ---------------- bf16-split tensor-core GEMM -------------------------------
// D[oc,px] = sum_c W[oc,c]*X[c,px].  Tile M=64 x PX=256, K-chunk 32, 8 warps
// (warp w: all 64 oc x 32 px).  Inputs pre-split hi/lo bf16; cp.async 2-stage.
// EPI: 0 none, 1 swish, 2 tanh(x*0.25)*vaux.
template<int EPI, bool SPLITOUT, bool DUAL>
__global__ void __launch_bounds__(256, 2) gemm_bf16(
    const bf16* __restrict__ Xh, const bf16* __restrict__ Xl,
    const bf16* __restrict__ Wh, const bf16* __restrict__ Wl,
    const float* __restrict__ bias, int IC, int NPIX,
    float* dstf, int dstf_stride,
    float* dstf2, int dst2_stride, int oc_split,
    bf16* dh, bf16* dl, int d_stride, int dst_oc_base,
    const float* vaux, int vaux_stride)
{
    extern __shared__ __align__(16) char sm[];
    const int tid = threadIdx.x;
    const int lane = tid & 31, warp = tid >> 5;
    const int px0 = blockIdx.x * 256;
    const int oc0 = blockIdx.y * 64;
    const int b   = blockIdx.z;
    const u32 smb = smem_u32(sm);

    const bf16* Xhb = Xh + (size_t)b * IC * NPIX;
    const bf16* Xlb = Xl + (size_t)b * IC * NPIX;

    const int ar = tid >> 2, ac = (tid & 3) * 8;
    const int bc = (tid & 31) * 8, br0 = tid >> 5;
    const int nk = IC >> 5;

    float c[4][4][4];
    #pragma unroll
    for (int i = 0; i < 4; i++)
        #pragma unroll
        for (int j = 0; j < 4; j++)
            #pragma unroll
            for (int q = 0; q < 4; q++) c[i][j][q] = 0.f;

    auto issue = [&](int it) {
        const int st = it & 1;
        const int k0 = it << 5;
        u32 aD = smb + st * 2 * APB + (u32)(ar * APITCH + ac) * 2;
        const size_t aO = (size_t)(oc0 + ar) * IC + k0 + ac;
        cpa16(aD, Wh + aO);
        cpa16(aD + APB, Wl + aO);
        const u32 bBase = smb + 4 * APB + st * 2 * BPB;
        #pragma unroll
        for (int i = 0; i < 4; i++) {
            const int brr = br0 + i * 8;
            u32 bD = bBase + (u32)(brr * BPITCH + bc) * 2;
            const size_t bO = (size_t)(k0 + brr) * NPIX + px0 + bc;
            cpa16(bD, Xhb + bO);
            cpa16(bD + BPB, Xlb + bO);
        }
        cp_commit();
    };

    issue(0);

    const int grp = lane >> 3, lr = lane & 7;
    const int r8  = (grp & 1) * 8 + lr;
    const int kh8 = (grp >> 1) * 8;
    const int wn32 = warp * 32;

    for (int it = 0; it < nk; it++) {
        if (it + 1 < nk) { issue(it + 1); cp_wait<1>(); }
        else             { cp_wait<0>(); }
        __syncthreads();
        const int st = it & 1;
        const u32 aHi = smb + st * 2 * APB, aLo = aHi + APB;
        const u32 bHi = smb + 4 * APB + st * 2 * BPB, bLo = bHi + BPB;
        #pragma unroll
        for (int ks = 0; ks < 2; ks++) {
            u32 bh[2][4], bl[2][4];
            #pragma unroll
            for (int g = 0; g < 2; g++) {
                const u32 off = (u32)((ks * 16 + r8) * BPITCH + wn32 + g * 16 + kh8) * 2;
                ldm_x4t(bHi + off, bh[g][0], bh[g][1], bh[g][2], bh[g][3]);
                ldm_x4t(bLo + off, bl[g][0], bl[g][1], bl[g][2], bl[g][3]);
            }
            #pragma unroll
            for (int mi = 0; mi < 4; mi++) {
                u32 ah[4], al[4];
                const u32 aoff = (u32)((mi * 16 + r8) * APITCH + ks * 16 + kh8) * 2;
                ldm_x4(aHi + aoff, ah[0], ah[1], ah[2], ah[3]);
                ldm_x4(aLo + aoff, al[0], al[1], al[2], al[3]);
                #pragma unroll
                for (int nj = 0; nj < 4; nj++) {
                    const int g = nj >> 1, s2 = nj & 1;
                    mma_bf16(c[mi][nj], ah, bh[g][2 * s2], bh[g][2 * s2 + 1]);
                    mma_bf16(c[mi][nj], ah, bl[g][2 * s2], bl[g][2 * s2 + 1]);
                    mma_bf16(c[mi][nj], al, bh[g][2 * s2], bh[g][2 * s2 + 1]);
                }
            }
        }
        __syncthreads();
    }

    // ---- epilogue
    const int r4 = lane >> 2, c2 = (lane & 3) * 2;
    #pragma unroll
    for (int mi = 0; mi < 4; mi++) {
        #pragma unroll
        for (int h = 0; h < 2; h++) {
            const int oc = oc0 + mi * 16 + h * 8 + r4;
            const float bv = bias[oc];
            #pragma unroll
            for (int nj = 0; nj < 4; nj++) {
                const int px = px0 + wn32 + nj * 8 + c2;
                float v0 = c[mi][nj][h * 2]     + bv;
                float v1 = c[mi][nj][h * 2 + 1] + bv;
                if (EPI == 1) {
                    v0 = v0 / (1.f + __expf(-v0));
                    v1 = v1 / (1.f + __expf(-v1));
                } else if (EPI == 2) {
                    const float* vr = vaux + (size_t)b * vaux_stride
                                    + (size_t)oc * NPIX + px;
                    v0 = tanhf(v0 * 0.25f) * __ldg(vr);
                    v1 = tanhf(v1 * 0.25f) * __ldg(vr + 1);
                }
                if (SPLITOUT) {
                    u32 hp, lp; split2(v0, v1, hp, lp);
                    const size_t o = (size_t)b * d_stride
                                   + (size_t)(dst_oc_base + oc) * NPIX + px;
                    *reinterpret_cast<u32*>(dh + o) = hp;
                    *reinterpret_cast<u32*>(dl + o) = lp;
                } else if (DUAL) {
                    if (oc < oc_split)
                        *reinterpret_cast<float2*>(dstf + (size_t)b * dstf_stride
                            + (size_t)oc * NPIX + px) = make_float2(v0, v1);
                    else
                        *reinterpret_cast<float2*>(dstf2 + (size_t)b * dst2_stride
                            + (size_t)(oc - oc_split) * NPIX + px) = make_float2(v0, v1);
                } else {
                    *reinterpret_cast<float2*>(dstf + (size_t)b * dstf_stride
                        + (size_t)oc * NPIX + px) = make_float2(v0, v1);
                }
            }
        }
    }
}

// ---------------- weight prep: fp32 -> hi/lo bf16 ---------------------------
__global__ void prep_weights(
    const float* __restrict__ Wqkv, const float* __restrict__ Wq,
    const float* __restrict__ Wa1, const float* __restrict__ Wa2,
    const float* __restrict__ Wkv, const float* __restrict__ Wproj,
    const float* __restrict__ bqkv, const float* __restrict__ bq)
{
    const int i = blockIdx.x * 256 + threadIdx.x;
    if (i < 32768) {                       // W1 = [Wqkv; Wq] 256x128
        float v = (i < 24576) ? Wqkv[i] : Wq[i - 24576];
        split1(v, g_w1h, g_w1l, i);
    } else if (i < 36864) {                // Wa1 64x64
        split1(Wa1[i - 32768], g_wa1h, g_wa1l, i - 32768);
    } else if (i < 40960) {                // Wa2 64x64
        split1(Wa2[i - 36864], g_wa2h, g_wa2l, i - 36864);
    } else if (i < 57344) {                // Wkv 128x128
        split1(Wkv[i - 40960], g_wkvh, g_wkvl, i - 40960);
    } else if (i < 73728) {                // Wproj 128x128
        split1(Wproj[i - 57344], g_wph, g_wpl, i - 57344);
    } else if (i < 73984) {                // stacked bias
        const int j = i - 73728;
        g_b1[j] = (j < 192) ? bqkv[j] : bq[j - 192];
    }
}

// ---------------- x -> hi/lo bf16 --------------------------------------------
__global__ void cvt_split(const float* __restrict__ x,
                          bf16* __restrict__ h, bf16* __restrict__ l)
{
    const size_t i = ((size_t)blockIdx.x * 256 + threadIdx.x) * 4;
    float4 v = *reinterpret_cast<const float4*>(x + i);
    u32 hp0, lp0, hp1, lp1;
    split2(v.x, v.y, hp0, lp0);
    split2(v.z, v.w, hp1, lp1);
    *reinterpret_cast<uint2*>(h + i) = make_uint2(hp0, hp1);
    *reinterpret_cast<uint2*>(l + i) = make_uint2(lp0, lp1);
}

// ---------------- depthwise 3x3 + q*k fusion --------------------------------
__device__ __forceinline__ float conv_at(const float* __restrict__ sp,
                                         const float* __restrict__ w, float bv,
                                         int x, int y)
{
    float s = bv;
    #pragma unroll
    for (int dy = -1; dy <= 1; dy++) {
        const int yy = y + dy;
        if (yy < 0 || yy >= HH) continue;
        #pragma unroll
        for (int dx = -1; dx <= 1; dx++) {
            const int xx = x + dx;
            if (xx < 0 || xx >= WW) continue;
            s += w[(dy + 1) * 3 + (dx + 1)] * __ldg(&sp[yy * WW + xx]);
        }
    }
    return s;
}

__global__ void dwconv_qk(const float* __restrict__ qkv,
                          const float* __restrict__ w,
                          const float* __restrict__ bias,
                          bf16* __restrict__ qkh, bf16* __restrict__ qkl,
                          float* __restrict__ v)
{
    const int z = blockIdx.z;
    const int b = z >> 7, t = z & 127;
    const int x = blockIdx.x * 32 + threadIdx.x;
    const int y = blockIdx.y * 8 + threadIdx.y;

    if (t < 64) {
        const float sq = conv_at(qkv + ((size_t)b * 192 + t) * HW,
                                 w + t * 9, __ldg(&bias[t]), x, y);
        const float sk = conv_at(qkv + ((size_t)b * 192 + t + 64) * HW,
                                 w + (t + 64) * 9, __ldg(&bias[t + 64]), x, y);
        split1(sq * sk, qkh, qkl, ((size_t)b * 64 + t) * HW + y * WW + x);
    } else {
        const int cv = t - 64;
        const float sv = conv_at(qkv + ((size_t)b * 192 + 128 + cv) * HW,
                                 w + (128 + cv) * 9, __ldg(&bias[128 + cv]), x, y);
        v[((size_t)b * 64 + cv) * HW + y * WW + x] = sv;
    }
}

// ---------------- 8x8 avgpool -> hi/lo bf16 ----------------------------------
__global__ void avgpool8(const float* __restrict__ x,
                         bf16* __restrict__ xph, bf16* __restrict__ xpl)
{
    const int idx = blockIdx.x * 256 + threadIdx.x;
    const int pos = idx & 255;
    const int j = pos & 15, i = pos >> 4;
    const int bc = idx >> 8;
    const float* sp = x + (size_t)bc * HW + (i * 8) * WW + j * 8;
    float s = 0.f;
    #pragma unroll
    for (int r = 0; r < 8; r++) {
        const float4 a = *reinterpret_cast<const float4*>(sp + r * WW);
        const float4 b = *reinterpret_cast<const float4*>(sp + r * WW + 4);
        s += a.x + a.y + a.z + a.w + b.x + b.y + b.z + b.w;
    }
    split1(s * (1.f / 64.f), xph, xpl, idx);
}

// ---------------- low-freq softmax attention --------------------------------
__global__ void __launch_bounds__(128) lowfreq_attn(
    const float* __restrict__ qg, const float* __restrict__ kv,
    bf16* __restrict__ ch, bf16* __restrict__ cl)
{
    const int b = blockIdx.z, h = blockIdx.y;
    const int p = blockIdx.x * 128 + threadIdx.x;

    __shared__ __align__(16) u64 ks2[256][8];
    __shared__ __align__(16) u64 vs2[256][8];

    const float* kvb = kv + (size_t)b * 128 * 256;
    for (int i = threadIdx.x; i < 2048; i += 128) {
        const int d2 = i >> 8, m = i & 255;
        ks2[m][d2] = pack2(kvb[(h * 16 + 2 * d2) * 256 + m],
                           kvb[(h * 16 + 2 * d2 + 1) * 256 + m]);
        vs2[m][d2] = pack2(kvb[(64 + h * 16 + 2 * d2) * 256 + m],
                           kvb[(64 + h * 16 + 2 * d2 + 1) * 256 + m]);
    }
    __syncthreads();

    u64 q2[8];
    #pragma unroll
    for (int d2 = 0; d2 < 8; d2++) {
        const size_t base = (size_t)b * 64 * HW + (size_t)(h * 16 + 2 * d2) * HW + p;
        q2[d2] = pack2(0.25f * __ldg(&qg[base]), 0.25f * __ldg(&qg[base + HW]));
    }

    float mx = -1e30f, sum = 0.f;
    u64 acc2[8];
    #pragma unroll
    for (int d2 = 0; d2 < 8; d2++) acc2[d2] = 0ull;

    for (int m = 0; m < 256; m++) {
        u64 s2 = 0ull;
        #pragma unroll
        for (int d2 = 0; d2 < 8; d2++) s2 = ffma2(q2[d2], ks2[m][d2], s2);
        float slo, shi; unpack2(s2, slo, shi);
        const float s = slo + shi;
        if (s > mx) {
            const float corr = __expf(mx - s);
            const u64 c2 = pack2(corr, corr);
            sum = sum * corr + 1.f;
            #pragma unroll
            for (int d2 = 0; d2 < 8; d2++) acc2[d2] = ffma2(acc2[d2], c2, vs2[m][d2]);
            mx = s;
        } else {
            const float e = __expf(s - mx);
            const u64 e2 = pack2(e, e);
            sum += e;
            #pragma unroll
            for (int d2 = 0; d2 < 8; d2++) acc2[d2] = ffma2(e2, vs2[m][d2], acc2[d2]);
        }
    }

    const float inv = 1.f / sum;
    #pragma unroll
    for (int d2 = 0; d2 < 8; d2++) {
        float lo, hi; unpack2(acc2[d2], lo, hi);
        const size_t base = ((size_t)b * 128 + 64 + h * 16 + 2 * d2) * HW + p;
        split1(lo * inv, ch, cl, base);
        split1(hi * inv, ch, cl, base + HW);
    }
}

// ---------------- launch -----------------------------------------------------
extern "C" void kernel_launch(void* const* d_in, const int* in_sizes, int n_in,
                              void* d_out, int out_size)
{
    const float* x     = (const float*)d_in[0];
    const float* Wqkv  = (const float*)d_in[1];
    const float* Wdw   = (const float*)d_in[3];
    const float* bdw   = (const float*)d_in[4];
    const float* Wa1   = (const float*)d_in[5];
    const float* ba1   = (const float*)d_in[6];
    const float* Wa2   = (const float*)d_in[7];
    const float* ba2   = (const float*)d_in[8];
    const float* Wq    = (const float*)d_in[9];
    const float* bkv   = (const float*)d_in[12];
    const float* Wkv   = (const float*)d_in[11];
    const float* Wproj = (const float*)d_in[13];
    const float* bproj = (const float*)d_in[14];
    const float* bqkv  = (const float*)d_in[2];
    const float* bq    = (const float*)d_in[10];
    float* out = (float*)d_out;

    float *qkv, *v, *qg, *kv, *b1;
    bf16 *xh, *xl, *qkh, *qkl, *ah, *al, *ch, *cl, *xph, *xpl;
    bf16 *w1h, *w1l, *wa1h, *wa1l, *wa2h, *wa2l, *wkvh, *wkvl, *wph, *wpl;
    cudaGetSymbolAddress((void**)&qkv, g_qkv);
    cudaGetSymbolAddress((void**)&v,   g_v);
    cudaGetSymbolAddress((void**)&qg,  g_qg);
    cudaGetSymbolAddress((void**)&kv,  g_kv);
    cudaGetSymbolAddress((void**)&b1,  g_b1);
    cudaGetSymbolAddress((void**)&xh,  g_xh);
    cudaGetSymbolAddress((void**)&xl,  g_xl);
    cudaGetSymbolAddress((void**)&qkh, g_qkh);
    cudaGetSymbolAddress((void**)&qkl, g_qkl);
    cudaGetSymbolAddress((void**)&ah,  g_ah);
    cudaGetSymbolAddress((void**)&al,  g_al);
    cudaGetSymbolAddress((void**)&ch,  g_ch);
    cudaGetSymbolAddress((void**)&cl,  g_cl);
    cudaGetSymbolAddress((void**)&xph, g_xph);
    cudaGetSymbolAddress((void**)&xpl, g_xpl);
    cudaGetSymbolAddress((void**)&w1h, g_w1h);
    cudaGetSymbolAddress((void**)&w1l, g_w1l);
    cudaGetSymbolAddress((void**)&wa1h, g_wa1h);
    cudaGetSymbolAddress((void**)&wa1l, g_wa1l);
    cudaGetSymbolAddress((void**)&wa2h, g_wa2h);
    cudaGetSymbolAddress((void**)&wa2l, g_wa2l);
    cudaGetSymbolAddress((void**)&wkvh, g_wkvh);
    cudaGetSymbolAddress((void**)&wkvl, g_wkvl);
    cudaGetSymbolAddress((void**)&wph, g_wph);
    cudaGetSymbolAddress((void**)&wpl, g_wpl);

    cudaFuncSetAttribute(gemm_bf16<0, false, true>,
                         cudaFuncAttributeMaxDynamicSharedMemorySize, SMEM_BYTES);
    cudaFuncSetAttribute(gemm_bf16<1, true, false>,
                         cudaFuncAttributeMaxDynamicSharedMemorySize, SMEM_BYTES);
    cudaFuncSetAttribute(gemm_bf16<2, true, false>,
                         cudaFuncAttributeMaxDynamicSharedMemorySize, SMEM_BYTES);
    cudaFuncSetAttribute(gemm_bf16<0, false, false>,
                         cudaFuncAttributeMaxDynamicSharedMemorySize, SMEM_BYTES);

    // 0) weight prep + x split
    prep_weights<<<289, 256>>>(Wqkv, Wq, Wa1, Wa2, Wkv, Wproj, bqkv, bq);
    cvt_split<<<NB * 128 * HW / 1024, 256>>>(x, xh, xl);

    // 1) fused qkv+qg GEMM: OC=256 over x
    gemm_bf16<0, false, true><<<dim3(HW / 256, 4, NB), 256, SMEM_BYTES>>>(
        xh, xl, w1h, w1l, b1, 128, HW,
        qkv, 192 * HW, qg, 64 * HW, 192,
        nullptr, nullptr, 0, 0, nullptr, 0);

    // 2) depthwise 3x3 with q*k fusion
    dwconv_qk<<<dim3(4, 16, NB * 128), dim3(32, 8)>>>(qkv, Wdw, bdw, qkh, qkl, v);

    // 3) a = swish(Wa1 @ qk)
    gemm_bf16<1, true, false><<<dim3(HW / 256, 1, NB), 256, SMEM_BYTES>>>(
        qkh, qkl, wa1h, wa1l, ba1, 64, HW,
        nullptr, 0, nullptr, 0, 0,
        ah, al, 64 * HW, 0, nullptr, 0);

    // 4) res_h = tanh((Wa2 @ a)*0.25)*v -> cat planes [0,64)
    gemm_bf16<2, true, false><<<dim3(HW / 256, 1, NB), 256, SMEM_BYTES>>>(
        ah, al, wa2h, wa2l, ba2, 64, HW,
        nullptr, 0, nullptr, 0, 0,
        ch, cl, 128 * HW, 0, v, 64 * HW);

    // 5) avgpool 8x8 -> split
    avgpool8<<<NB * 128 * 256 / 256, 256>>>(x, xph, xpl);

    // 6) kv = Wkv @ xp
    gemm_bf16<0, false, false><<<dim3(1, 2, NB), 256, SMEM_BYTES>>>(
        xph, xpl, wkvh, wkvl, bkv, 128, 256,
        kv, 128 * 256, nullptr, 0, 0,
        nullptr, nullptr, 0, 0, nullptr, 0);

    // 7) low-freq attention -> cat planes [64,128)
    lowfreq_attn<<<dim3(HW / 128, 4, NB), 128>>>(qg, kv, ch, cl);

    // 8) out = Wproj @ cat
    gemm_bf16<0, false, false><<<dim3(HW / 256, 2, NB), 256, SMEM_BYTES>>>(
        ch, cl, wph, wpl, bproj, 128, HW,
        out, 128 * HW, nullptr, 0, 0,
        nullptr, nullptr, 0, 0, nullptr, 0);
}

// round 6
// speedup vs baseline: 2.0407x; 1.4135x over previous
#include <cuda_runtime.h>
#include <cuda_bf16.h>
#include <math.h>

#define HW 16384
#define HH 128
#define WW 128
#define NB 4

typedef unsigned long long u64;
typedef unsigned int u32;
typedef __nv_bfloat16 bf16;

// ---------------- f32x2 helpers (attention) ---------------------------------
__device__ __forceinline__ u64 pack2(float lo, float hi) {
    u64 r; asm("mov.b64 %0,{%1,%2};" : "=l"(r) : "f"(lo), "f"(hi)); return r;
}
__device__ __forceinline__ void unpack2(u64 v, float& lo, float& hi) {
    asm("mov.b64 {%0,%1},%2;" : "=f"(lo), "=f"(hi) : "l"(v));
}
__device__ __forceinline__ u64 ffma2(u64 a, u64 b, u64 c) {
    u64 r; asm("fma.rn.f32x2 %0,%1,%2,%3;" : "=l"(r) : "l"(a), "l"(b), "l"(c)); return r;
}

// ---------------- scratch ----------------------------------------------------
__device__ __align__(256) float g_qkv [NB * 192 * HW];
__device__ __align__(256) float g_v   [NB * 64  * HW];
__device__ __align__(256) float g_qg  [NB * 64  * HW];
__device__ __align__(256) float g_kv  [NB * 128 * 256];
__device__ __align__(256) bf16  g_xh  [NB * 128 * HW];
__device__ __align__(256) bf16  g_xl  [NB * 128 * HW];
__device__ __align__(256) bf16  g_qkh [NB * 64 * HW];
__device__ __align__(256) bf16  g_qkl [NB * 64 * HW];
__device__ __align__(256) bf16  g_ah  [NB * 64 * HW];
__device__ __align__(256) bf16  g_al  [NB * 64 * HW];
__device__ __align__(256) bf16  g_ch  [NB * 128 * HW];
__device__ __align__(256) bf16  g_cl  [NB * 128 * HW];
__device__ __align__(256) bf16  g_xph [NB * 128 * 256];
__device__ __align__(256) bf16  g_xpl [NB * 128 * 256];
__device__ __align__(256) bf16  g_w1h [256 * 128];
__device__ __align__(256) bf16  g_w1l [256 * 128];
__device__ __align__(256) bf16  g_wa1h[64 * 64];
__device__ __align__(256) bf16  g_wa1l[64 * 64];
__device__ __align__(256) bf16  g_wa2h[64 * 64];
__device__ __align__(256) bf16  g_wa2l[64 * 64];
__device__ __align__(256) bf16  g_wkvh[128 * 128];
__device__ __align__(256) bf16  g_wkvl[128 * 128];
__device__ __align__(256) bf16  g_wph [128 * 128];
__device__ __align__(256) bf16  g_wpl [128 * 128];
__device__ __align__(256) float g_b1  [256];

// ---------------- mma / cp.async helpers ------------------------------------
__device__ __forceinline__ u32 smem_u32(const void* p) {
    u32 a;
    asm("{ .reg .u64 t; cvta.to.shared.u64 t, %1; cvt.u32.u64 %0, t; }"
        : "=r"(a) : "l"(p));
    return a;
}
__device__ __forceinline__ void ldm_x4(u32 a, u32& r0, u32& r1, u32& r2, u32& r3) {
    asm volatile("ldmatrix.sync.aligned.m8n8.x4.shared.b16 {%0,%1,%2,%3},[%4];"
                 : "=r"(r0), "=r"(r1), "=r"(r2), "=r"(r3) : "r"(a));
}
__device__ __forceinline__ void ldm_x4t(u32 a, u32& r0, u32& r1, u32& r2, u32& r3) {
    asm volatile("ldmatrix.sync.aligned.m8n8.x4.trans.shared.b16 {%0,%1,%2,%3},[%4];"
                 : "=r"(r0), "=r"(r1), "=r"(r2), "=r"(r3) : "r"(a));
}
__device__ __forceinline__ void mma_bf16(float* c, const u32* a, u32 b0, u32 b1) {
    asm volatile(
        "mma.sync.aligned.m16n8k16.row.col.f32.bf16.bf16.f32 "
        "{%0,%1,%2,%3},{%4,%5,%6,%7},{%8,%9},{%0,%1,%2,%3};"
        : "+f"(c[0]), "+f"(c[1]), "+f"(c[2]), "+f"(c[3])
        : "r"(a[0]), "r"(a[1]), "r"(a[2]), "r"(a[3]), "r"(b0), "r"(b1));
}
__device__ __forceinline__ void cpa16(u32 d, const void* s) {
    asm volatile("cp.async.cg.shared.global [%0],[%1],16;" :: "r"(d), "l"(s));
}
__device__ __forceinline__ void cp_commit() {
    asm volatile("cp.async.commit_group;" ::: "memory");
}
template<int N> __device__ __forceinline__ void cp_wait() {
    asm volatile("cp.async.wait_group %0;" :: "n"(N) : "memory");
}
__device__ __forceinline__ void split2(float x0, float x1, u32& h, u32& l) {
    bf16 h0 = __float2bfloat16(x0);
    bf16 h1 = __float2bfloat16(x1);
    float r0 = x0 - __bfloat162float(h0);
    float r1 = x1 - __bfloat162float(h1);
    __nv_bfloat162 hp; hp.x = h0; hp.y = h1;
    __nv_bfloat162 lp; lp.x = __float2bfloat16(r0); lp.y = __float2bfloat16(r1);
    h = *reinterpret_cast<u32*>(&hp);
    l = *reinterpret_cast<u32*>(&lp);
}
__device__ __forceinline__ void split1(float x, bf16* hd, bf16* ld, size_t o) {
    bf16 h = __float2bfloat16(x);
    hd[o] = h;
    ld[o] = __float2bfloat16(x - __bfloat162float(h));
}

// ---------------- GEMM geometry ----------------------------------------------
#define APITCH 40
#define BPITCH 264
#define APB (64 * APITCH * 2)
#define BPB (32 * BPITCH * 2)
#define SMEM_BYTES (4 * APB + 4 * BPB)

// ---------------- bf16-split tensor-core GEMM -------------------------------
template<int EPI, bool SPLITOUT, bool DUAL>
__global__ void __launch_bounds__(256, 2) gemm_bf16(
    const bf16* __restrict__ Xh, const bf16* __restrict__ Xl,
    const bf16* __restrict__ Wh, const bf16* __restrict__ Wl,
    const float* __restrict__ bias, int IC, int NPIX,
    float* dstf, int dstf_stride,
    float* dstf2, int dst2_stride, int oc_split,
    bf16* dh, bf16* dl, int d_stride, int dst_oc_base,
    const float* vaux, int vaux_stride)
{
    extern __shared__ __align__(16) char sm[];
    const int tid = threadIdx.x;
    const int lane = tid & 31, warp = tid >> 5;
    const int px0 = blockIdx.x * 256;
    const int oc0 = blockIdx.y * 64;
    const int b   = blockIdx.z;
    const u32 smb = smem_u32(sm);

    const bf16* Xhb = Xh + (size_t)b * IC * NPIX;
    const bf16* Xlb = Xl + (size_t)b * IC * NPIX;

    const int ar = tid >> 2, ac = (tid & 3) * 8;
    const int bc = (tid & 31) * 8, br0 = tid >> 5;
    const int nk = IC >> 5;

    float c[4][4][4];
    #pragma unroll
    for (int i = 0; i < 4; i++)
        #pragma unroll
        for (int j = 0; j < 4; j++)
            #pragma unroll
            for (int q = 0; q < 4; q++) c[i][j][q] = 0.f;

    auto issue = [&](int it) {
        const int st = it & 1;
        const int k0 = it << 5;
        u32 aD = smb + st * 2 * APB + (u32)(ar * APITCH + ac) * 2;
        const size_t aO = (size_t)(oc0 + ar) * IC + k0 + ac;
        cpa16(aD, Wh + aO);
        cpa16(aD + APB, Wl + aO);
        const u32 bBase = smb + 4 * APB + st * 2 * BPB;
        #pragma unroll
        for (int i = 0; i < 4; i++) {
            const int brr = br0 + i * 8;
            u32 bD = bBase + (u32)(brr * BPITCH + bc) * 2;
            const size_t bO = (size_t)(k0 + brr) * NPIX + px0 + bc;
            cpa16(bD, Xhb + bO);
            cpa16(bD + BPB, Xlb + bO);
        }
        cp_commit();
    };

    issue(0);

    const int grp = lane >> 3, lr = lane & 7;
    const int r8  = (grp & 1) * 8 + lr;
    const int kh8 = (grp >> 1) * 8;
    const int wn32 = warp * 32;

    for (int it = 0; it < nk; it++) {
        if (it + 1 < nk) { issue(it + 1); cp_wait<1>(); }
        else             { cp_wait<0>(); }
        __syncthreads();
        const int st = it & 1;
        const u32 aHi = smb + st * 2 * APB, aLo = aHi + APB;
        const u32 bHi = smb + 4 * APB + st * 2 * BPB, bLo = bHi + BPB;
        #pragma unroll
        for (int ks = 0; ks < 2; ks++) {
            u32 bh[2][4], bl[2][4];
            #pragma unroll
            for (int g = 0; g < 2; g++) {
                const u32 off = (u32)((ks * 16 + r8) * BPITCH + wn32 + g * 16 + kh8) * 2;
                ldm_x4t(bHi + off, bh[g][0], bh[g][1], bh[g][2], bh[g][3]);
                ldm_x4t(bLo + off, bl[g][0], bl[g][1], bl[g][2], bl[g][3]);
            }
            #pragma unroll
            for (int mi = 0; mi < 4; mi++) {
                u32 ah[4], al[4];
                const u32 aoff = (u32)((mi * 16 + r8) * APITCH + ks * 16 + kh8) * 2;
                ldm_x4(aHi + aoff, ah[0], ah[1], ah[2], ah[3]);
                ldm_x4(aLo + aoff, al[0], al[1], al[2], al[3]);
                #pragma unroll
                for (int nj = 0; nj < 4; nj++) {
                    const int g = nj >> 1, s2 = nj & 1;
                    mma_bf16(c[mi][nj], ah, bh[g][2 * s2], bh[g][2 * s2 + 1]);
                    mma_bf16(c[mi][nj], ah, bl[g][2 * s2], bl[g][2 * s2 + 1]);
                    mma_bf16(c[mi][nj], al, bh[g][2 * s2], bh[g][2 * s2 + 1]);
                }
            }
        }
        __syncthreads();
    }

    // ---- epilogue
    const int r4 = lane >> 2, c2 = (lane & 3) * 2;
    #pragma unroll
    for (int mi = 0; mi < 4; mi++) {
        #pragma unroll
        for (int h = 0; h < 2; h++) {
            const int oc = oc0 + mi * 16 + h * 8 + r4;
            const float bv = bias[oc];
            #pragma unroll
            for (int nj = 0; nj < 4; nj++) {
                const int px = px0 + wn32 + nj * 8 + c2;
                float v0 = c[mi][nj][h * 2]     + bv;
                float v1 = c[mi][nj][h * 2 + 1] + bv;
                if (EPI == 1) {
                    v0 = v0 / (1.f + __expf(-v0));
                    v1 = v1 / (1.f + __expf(-v1));
                } else if (EPI == 2) {
                    const float* vr = vaux + (size_t)b * vaux_stride
                                    + (size_t)oc * NPIX + px;
                    v0 = tanhf(v0 * 0.25f) * __ldg(vr);
                    v1 = tanhf(v1 * 0.25f) * __ldg(vr + 1);
                }
                if (SPLITOUT) {
                    u32 hp, lp; split2(v0, v1, hp, lp);
                    const size_t o = (size_t)b * d_stride
                                   + (size_t)(dst_oc_base + oc) * NPIX + px;
                    *reinterpret_cast<u32*>(dh + o) = hp;
                    *reinterpret_cast<u32*>(dl + o) = lp;
                } else if (DUAL) {
                    if (oc < oc_split)
                        *reinterpret_cast<float2*>(dstf + (size_t)b * dstf_stride
                            + (size_t)oc * NPIX + px) = make_float2(v0, v1);
                    else
                        *reinterpret_cast<float2*>(dstf2 + (size_t)b * dst2_stride
                            + (size_t)(oc - oc_split) * NPIX + px) = make_float2(v0, v1);
                } else {
                    *reinterpret_cast<float2*>(dstf + (size_t)b * dstf_stride
                        + (size_t)oc * NPIX + px) = make_float2(v0, v1);
                }
            }
        }
    }
}

// ---------------- weight prep ------------------------------------------------
__global__ void prep_weights(
    const float* __restrict__ Wqkv, const float* __restrict__ Wq,
    const float* __restrict__ Wa1, const float* __restrict__ Wa2,
    const float* __restrict__ Wkv, const float* __restrict__ Wproj,
    const float* __restrict__ bqkv, const float* __restrict__ bq)
{
    const int i = blockIdx.x * 256 + threadIdx.x;
    if (i < 32768) {
        float v = (i < 24576) ? Wqkv[i] : Wq[i - 24576];
        split1(v, g_w1h, g_w1l, i);
    } else if (i < 36864) {
        split1(Wa1[i - 32768], g_wa1h, g_wa1l, i - 32768);
    } else if (i < 40960) {
        split1(Wa2[i - 36864], g_wa2h, g_wa2l, i - 36864);
    } else if (i < 57344) {
        split1(Wkv[i - 40960], g_wkvh, g_wkvl, i - 40960);
    } else if (i < 73728) {
        split1(Wproj[i - 57344], g_wph, g_wpl, i - 57344);
    } else if (i < 73984) {
        const int j = i - 73728;
        g_b1[j] = (j < 192) ? bqkv[j] : bq[j - 192];
    }
}

// ---------------- x -> hi/lo bf16 --------------------------------------------
__global__ void cvt_split(const float* __restrict__ x,
                          bf16* __restrict__ h, bf16* __restrict__ l)
{
    const size_t i = ((size_t)blockIdx.x * 256 + threadIdx.x) * 4;
    float4 v = *reinterpret_cast<const float4*>(x + i);
    u32 hp0, lp0, hp1, lp1;
    split2(v.x, v.y, hp0, lp0);
    split2(v.z, v.w, hp1, lp1);
    *reinterpret_cast<uint2*>(h + i) = make_uint2(hp0, hp1);
    *reinterpret_cast<uint2*>(l + i) = make_uint2(lp0, lp1);
}

// ---------------- depthwise 3x3, smem-tiled rolling stencil -----------------
// Block: 128 threads (one per column), tile = 128 wide x 16 output rows.
// t<64: q & k planes convolved, product emitted split-bf16.  t>=64: v plane fp32.
__global__ void __launch_bounds__(128) dwconv_qk(
    const float* __restrict__ qkv, const float* __restrict__ w,
    const float* __restrict__ bias,
    bf16* __restrict__ qkh, bf16* __restrict__ qkl,
    float* __restrict__ vout)
{
    const int z = blockIdx.z;
    const int b = z >> 7, t = z & 127;
    const int x = threadIdx.x;
    const int y0 = blockIdx.y * 16;

    __shared__ float s0[18][136];
    __shared__ float s1[18][136];

    if (t < 64) {
        const float* pq = qkv + ((size_t)b * 192 + t) * HW;
        const float* pk = qkv + ((size_t)b * 192 + 64 + t) * HW;
        #pragma unroll
        for (int r = 0; r < 18; r++) {
            const int yy = y0 - 1 + r;
            const bool ok = (yy >= 0) && (yy < HH);
            s0[r][x + 1] = ok ? __ldg(pq + yy * WW + x) : 0.f;
            s1[r][x + 1] = ok ? __ldg(pk + yy * WW + x) : 0.f;
        }
        if (x < 2) {
            const int col = x ? 129 : 0;
            #pragma unroll
            for (int r = 0; r < 18; r++) { s0[r][col] = 0.f; s1[r][col] = 0.f; }
        }
        __syncthreads();

        float wq[9], wk[9];
        #pragma unroll
        for (int i = 0; i < 9; i++) {
            wq[i] = __ldg(&w[t * 9 + i]);
            wk[i] = __ldg(&w[(64 + t) * 9 + i]);
        }
        const float bq = __ldg(&bias[t]);
        const float bk = __ldg(&bias[64 + t]);

        bf16* oh = qkh + ((size_t)b * 64 + t) * HW + (size_t)y0 * WW + x;
        bf16* ol = qkl + ((size_t)b * 64 + t) * HW + (size_t)y0 * WW + x;

        float Aq = 0.f, Bq = 0.f, Ak = 0.f, Bk = 0.f;
        #pragma unroll
        for (int r = 0; r < 18; r++) {
            const float lq = s0[r][x], cq = s0[r][x + 1], rq = s0[r][x + 2];
            const float h0q = wq[0]*lq + wq[1]*cq + wq[2]*rq;
            const float h1q = wq[3]*lq + wq[4]*cq + wq[5]*rq;
            const float h2q = wq[6]*lq + wq[7]*cq + wq[8]*rq;
            const float lk = s1[r][x], ck = s1[r][x + 1], rk = s1[r][x + 2];
            const float h0k = wk[0]*lk + wk[1]*ck + wk[2]*rk;
            const float h1k = wk[3]*lk + wk[4]*ck + wk[5]*rk;
            const float h2k = wk[6]*lk + wk[7]*ck + wk[8]*rk;
            Aq += h2q; Ak += h2k;
            if (r >= 2) {
                const int o = r - 2;
                const float prod = (Aq + bq) * (Ak + bk);
                const bf16 hv = __float2bfloat16(prod);
                oh[o * WW] = hv;
                ol[o * WW] = __float2bfloat16(prod - __bfloat162float(hv));
            }
            Aq = Bq + h1q; Bq = h0q;
            Ak = Bk + h1k; Bk = h0k;
        }
    } else {
        const int cv = t - 64;
        const float* pv = qkv + ((size_t)b * 192 + 128 + cv) * HW;
        #pragma unroll
        for (int r = 0; r < 18; r++) {
            const int yy = y0 - 1 + r;
            s0[r][x + 1] = (yy >= 0 && yy < HH) ? __ldg(pv + yy * WW + x) : 0.f;
        }
        if (x < 2) {
            const int col = x ? 129 : 0;
            #pragma unroll
            for (int r = 0; r < 18; r++) s0[r][col] = 0.f;
        }
        __syncthreads();

        float wv[9];
        #pragma unroll
        for (int i = 0; i < 9; i++) wv[i] = __ldg(&w[(128 + cv) * 9 + i]);
        const float bv = __ldg(&bias[128 + cv]);

        float* ov = vout + ((size_t)b * 64 + cv) * HW + (size_t)y0 * WW + x;
        float A = 0.f, Bv = 0.f;
        #pragma unroll
        for (int r = 0; r < 18; r++) {
            const float lv = s0[r][x], cvv = s0[r][x + 1], rv = s0[r][x + 2];
            const float h0 = wv[0]*lv + wv[1]*cvv + wv[2]*rv;
            const float h1 = wv[3]*lv + wv[4]*cvv + wv[5]*rv;
            const float h2 = wv[6]*lv + wv[7]*cvv + wv[8]*rv;
            A += h2;
            if (r >= 2) ov[(r - 2) * WW] = A + bv;
            A = Bv + h1; Bv = h0;
        }
    }
}

// ---------------- 8x8 avgpool -> hi/lo bf16 ----------------------------------
__global__ void avgpool8(const float* __restrict__ x,
                         bf16* __restrict__ xph, bf16* __restrict__ xpl)
{
    const int idx = blockIdx.x * 256 + threadIdx.x;
    const int pos = idx & 255;
    const int j = pos & 15, i = pos >> 4;
    const int bc = idx >> 8;
    const float* sp = x + (size_t)bc * HW + (i * 8) * WW + j * 8;
    float s = 0.f;
    #pragma unroll
    for (int r = 0; r < 8; r++) {
        const float4 a = *reinterpret_cast<const float4*>(sp + r * WW);
        const float4 b = *reinterpret_cast<const float4*>(sp + r * WW + 4);
        s += a.x + a.y + a.z + a.w + b.x + b.y + b.z + b.w;
    }
    split1(s * (1.f / 64.f), xph, xpl, idx);
}

// ---------------- low-freq softmax attention (2 px/thread, no online max) ---
__global__ void __launch_bounds__(128) lowfreq_attn(
    const float* __restrict__ qg, const float* __restrict__ kv,
    bf16* __restrict__ ch, bf16* __restrict__ cl)
{
    const int b = blockIdx.z, h = blockIdx.y;
    const int p = blockIdx.x * 256 + threadIdx.x;   // pixels p and p+128

    __shared__ __align__(16) u64 ks2[256][8];
    __shared__ __align__(16) u64 vs2[256][8];

    const float* kvb = kv + (size_t)b * 128 * 256;
    for (int i = threadIdx.x; i < 2048; i += 128) {
        const int d2 = i >> 8, m = i & 255;
        ks2[m][d2] = pack2(kvb[(h * 16 + 2 * d2) * 256 + m],
                           kvb[(h * 16 + 2 * d2 + 1) * 256 + m]);
        vs2[m][d2] = pack2(kvb[(64 + h * 16 + 2 * d2) * 256 + m],
                           kvb[(64 + h * 16 + 2 * d2 + 1) * 256 + m]);
    }
    __syncthreads();

    u64 qa[8], qb[8];
    #pragma unroll
    for (int d2 = 0; d2 < 8; d2++) {
        const size_t base = (size_t)b * 64 * HW + (size_t)(h * 16 + 2 * d2) * HW + p;
        qa[d2] = pack2(0.25f * __ldg(&qg[base]),       0.25f * __ldg(&qg[base + HW]));
        qb[d2] = pack2(0.25f * __ldg(&qg[base + 128]), 0.25f * __ldg(&qg[base + HW + 128]));
    }

    float suma = 0.f, sumb = 0.f;
    u64 acca[8], accb[8];
    #pragma unroll
    for (int d2 = 0; d2 < 8; d2++) { acca[d2] = 0ull; accb[d2] = 0ull; }

    for (int m = 0; m < 256; m++) {
        u64 sa = 0ull, sb = 0ull;
        #pragma unroll
        for (int d2 = 0; d2 < 8; d2++) {
            const u64 kk = ks2[m][d2];
            sa = ffma2(qa[d2], kk, sa);
            sb = ffma2(qb[d2], kk, sb);
        }
        float a0, a1, b0, b1;
        unpack2(sa, a0, a1); unpack2(sb, b0, b1);
        const float ea = __expf(a0 + a1);
        const float eb = __expf(b0 + b1);
        suma += ea; sumb += eb;
        const u64 ea2 = pack2(ea, ea), eb2 = pack2(eb, eb);
        #pragma unroll
        for (int d2 = 0; d2 < 8; d2++) {
            const u64 vv = vs2[m][d2];
            acca[d2] = ffma2(ea2, vv, acca[d2]);
            accb[d2] = ffma2(eb2, vv, accb[d2]);
        }
    }

    const float inva = 1.f / suma, invb = 1.f / sumb;
    #pragma unroll
    for (int d2 = 0; d2 < 8; d2++) {
        float lo, hi;
        unpack2(acca[d2], lo, hi);
        const size_t base = ((size_t)b * 128 + 64 + h * 16 + 2 * d2) * HW + p;
        split1(lo * inva, ch, cl, base);
        split1(hi * inva, ch, cl, base + HW);
        unpack2(accb[d2], lo, hi);
        split1(lo * invb, ch, cl, base + 128);
        split1(hi * invb, ch, cl, base + HW + 128);
    }
}

// ---------------- launch -----------------------------------------------------
extern "C" void kernel_launch(void* const* d_in, const int* in_sizes, int n_in,
                              void* d_out, int out_size)
{
    const float* x     = (const float*)d_in[0];
    const float* Wqkv  = (const float*)d_in[1];
    const float* bqkv  = (const float*)d_in[2];
    const float* Wdw   = (const float*)d_in[3];
    const float* bdw   = (const float*)d_in[4];
    const float* Wa1   = (const float*)d_in[5];
    const float* ba1   = (const float*)d_in[6];
    const float* Wa2   = (const float*)d_in[7];
    const float* ba2   = (const float*)d_in[8];
    const float* Wq    = (const float*)d_in[9];
    const float* bq    = (const float*)d_in[10];
    const float* Wkv   = (const float*)d_in[11];
    const float* bkv   = (const float*)d_in[12];
    const float* Wproj = (const float*)d_in[13];
    const float* bproj = (const float*)d_in[14];
    float* out = (float*)d_out;

    float *qkv, *v, *qg, *kv, *b1;
    bf16 *xh, *xl, *qkh, *qkl, *ah, *al, *ch, *cl, *xph, *xpl;
    bf16 *w1h, *w1l, *wa1h, *wa1l, *wa2h, *wa2l, *wkvh, *wkvl, *wph, *wpl;
    cudaGetSymbolAddress((void**)&qkv, g_qkv);
    cudaGetSymbolAddress((void**)&v,   g_v);
    cudaGetSymbolAddress((void**)&qg,  g_qg);
    cudaGetSymbolAddress((void**)&kv,  g_kv);
    cudaGetSymbolAddress((void**)&b1,  g_b1);
    cudaGetSymbolAddress((void**)&xh,  g_xh);
    cudaGetSymbolAddress((void**)&xl,  g_xl);
    cudaGetSymbolAddress((void**)&qkh, g_qkh);
    cudaGetSymbolAddress((void**)&qkl, g_qkl);
    cudaGetSymbolAddress((void**)&ah,  g_ah);
    cudaGetSymbolAddress((void**)&al,  g_al);
    cudaGetSymbolAddress((void**)&ch,  g_ch);
    cudaGetSymbolAddress((void**)&cl,  g_cl);
    cudaGetSymbolAddress((void**)&xph, g_xph);
    cudaGetSymbolAddress((void**)&xpl, g_xpl);
    cudaGetSymbolAddress((void**)&w1h, g_w1h);
    cudaGetSymbolAddress((void**)&w1l, g_w1l);
    cudaGetSymbolAddress((void**)&wa1h, g_wa1h);
    cudaGetSymbolAddress((void**)&wa1l, g_wa1l);
    cudaGetSymbolAddress((void**)&wa2h, g_wa2h);
    cudaGetSymbolAddress((void**)&wa2l, g_wa2l);
    cudaGetSymbolAddress((void**)&wkvh, g_wkvh);
    cudaGetSymbolAddress((void**)&wkvl, g_wkvl);
    cudaGetSymbolAddress((void**)&wph, g_wph);
    cudaGetSymbolAddress((void**)&wpl, g_wpl);

    cudaFuncSetAttribute(gemm_bf16<0, false, true>,
                         cudaFuncAttributeMaxDynamicSharedMemorySize, SMEM_BYTES);
    cudaFuncSetAttribute(gemm_bf16<1, true, false>,
                         cudaFuncAttributeMaxDynamicSharedMemorySize, SMEM_BYTES);
    cudaFuncSetAttribute(gemm_bf16<2, true, false>,
                         cudaFuncAttributeMaxDynamicSharedMemorySize, SMEM_BYTES);
    cudaFuncSetAttribute(gemm_bf16<0, false, false>,
                         cudaFuncAttributeMaxDynamicSharedMemorySize, SMEM_BYTES);

    // 0) weight prep + x split
    prep_weights<<<289, 256>>>(Wqkv, Wq, Wa1, Wa2, Wkv, Wproj, bqkv, bq);
    cvt_split<<<NB * 128 * HW / 1024, 256>>>(x, xh, xl);

    // 1) fused qkv+qg GEMM: OC=256 over x
    gemm_bf16<0, false, true><<<dim3(HW / 256, 4, NB), 256, SMEM_BYTES>>>(
        xh, xl, w1h, w1l, b1, 128, HW,
        qkv, 192 * HW, qg, 64 * HW, 192,
        nullptr, nullptr, 0, 0, nullptr, 0);

    // 2) depthwise 3x3 with q*k fusion (smem rolling stencil)
    dwconv_qk<<<dim3(1, 8, NB * 128), 128>>>(qkv, Wdw, bdw, qkh, qkl, v);

    // 3) a = swish(Wa1 @ qk)
    gemm_bf16<1, true, false><<<dim3(HW / 256, 1, NB), 256, SMEM_BYTES>>>(
        qkh, qkl, wa1h, wa1l, ba1, 64, HW,
        nullptr, 0, nullptr, 0, 0,
        ah, al, 64 * HW, 0, nullptr, 0);

    // 4) res_h = tanh((Wa2 @ a)*0.25)*v -> cat planes [0,64)
    gemm_bf16<2, true, false><<<dim3(HW / 256, 1, NB), 256, SMEM_BYTES>>>(
        ah, al, wa2h, wa2l, ba2, 64, HW,
        nullptr, 0, nullptr, 0, 0,
        ch, cl, 128 * HW, 0, v, 64 * HW);

    // 5) avgpool 8x8 -> split
    avgpool8<<<NB * 128 * 256 / 256, 256>>>(x, xph, xpl);

    // 6) kv = Wkv @ xp
    gemm_bf16<0, false, false><<<dim3(1, 2, NB), 256, SMEM_BYTES>>>(
        xph, xpl, wkvh, wkvl, bkv, 128, 256,
        kv, 128 * 256, nullptr, 0, 0,
        nullptr, nullptr, 0, 0, nullptr, 0);

    // 7) low-freq attention -> cat planes [64,128)
    lowfreq_attn<<<dim3(HW / 256, 4, NB), 128>>>(qg, kv, ch, cl);

    // 8) out = Wproj @ cat
    gemm_bf16<0, false, false><<<dim3(HW / 256, 2, NB), 256, SMEM_BYTES>>>(
        ch, cl, wph, wpl, bproj, 128, HW,
        out, 128 * HW, nullptr, 0, 0,
        nullptr, nullptr, 0, 0, nullptr, 0);
}

// round 7
// speedup vs baseline: 2.1114x; 1.0347x over previous
#include <cuda_runtime.h>
#include <cuda_bf16.h>
#include <math.h>

#define HW 16384
#define HH 128
#define WW 128
#define NB 4

typedef unsigned long long u64;
typedef unsigned int u32;
typedef __nv_bfloat16 bf16;

// ---------------- f32x2 helpers (attention) ---------------------------------
__device__ __forceinline__ u64 pack2(float lo, float hi) {
    u64 r; asm("mov.b64 %0,{%1,%2};" : "=l"(r) : "f"(lo), "f"(hi)); return r;
}
__device__ __forceinline__ void unpack2(u64 v, float& lo, float& hi) {
    asm("mov.b64 {%0,%1},%2;" : "=f"(lo), "=f"(hi) : "l"(v));
}
__device__ __forceinline__ u64 ffma2(u64 a, u64 b, u64 c) {
    u64 r; asm("fma.rn.f32x2 %0,%1,%2,%3;" : "=l"(r) : "l"(a), "l"(b), "l"(c)); return r;
}

// ---------------- scratch ----------------------------------------------------
__device__ __align__(256) float g_qkv [NB * 192 * HW];
__device__ __align__(256) float g_v   [NB * 64  * HW];
__device__ __align__(256) float g_qg  [NB * 64  * HW];
__device__ __align__(256) float g_kv  [NB * 128 * 256];
__device__ __align__(256) float g_xp  [NB * 128 * 256];
__device__ __align__(256) bf16  g_xh  [NB * 128 * HW];
__device__ __align__(256) bf16  g_xl  [NB * 128 * HW];
__device__ __align__(256) bf16  g_qkh [NB * 64 * HW];
__device__ __align__(256) bf16  g_qkl [NB * 64 * HW];
__device__ __align__(256) bf16  g_ch  [NB * 128 * HW];
__device__ __align__(256) bf16  g_cl  [NB * 128 * HW];
__device__ __align__(256) bf16  g_w1h [256 * 128];
__device__ __align__(256) bf16  g_w1l [256 * 128];
__device__ __align__(256) bf16  g_wa1h[64 * 64];
__device__ __align__(256) bf16  g_wa1l[64 * 64];
__device__ __align__(256) bf16  g_wa2h[64 * 64];
__device__ __align__(256) bf16  g_wa2l[64 * 64];
__device__ __align__(256) bf16  g_wph [128 * 128];
__device__ __align__(256) bf16  g_wpl [128 * 128];
__device__ __align__(256) float g_b1  [256];

// ---------------- mma / cp.async helpers ------------------------------------
__device__ __forceinline__ u32 smem_u32(const void* p) {
    u32 a;
    asm("{ .reg .u64 t; cvta.to.shared.u64 t, %1; cvt.u32.u64 %0, t; }"
        : "=r"(a) : "l"(p));
    return a;
}
__device__ __forceinline__ void ldm_x4(u32 a, u32& r0, u32& r1, u32& r2, u32& r3) {
    asm volatile("ldmatrix.sync.aligned.m8n8.x4.shared.b16 {%0,%1,%2,%3},[%4];"
                 : "=r"(r0), "=r"(r1), "=r"(r2), "=r"(r3) : "r"(a));
}
__device__ __forceinline__ void ldm_x4t(u32 a, u32& r0, u32& r1, u32& r2, u32& r3) {
    asm volatile("ldmatrix.sync.aligned.m8n8.x4.trans.shared.b16 {%0,%1,%2,%3},[%4];"
                 : "=r"(r0), "=r"(r1), "=r"(r2), "=r"(r3) : "r"(a));
}
__device__ __forceinline__ void mma_bf16(float* c, const u32* a, u32 b0, u32 b1) {
    asm volatile(
        "mma.sync.aligned.m16n8k16.row.col.f32.bf16.bf16.f32 "
        "{%0,%1,%2,%3},{%4,%5,%6,%7},{%8,%9},{%0,%1,%2,%3};"
        : "+f"(c[0]), "+f"(c[1]), "+f"(c[2]), "+f"(c[3])
        : "r"(a[0]), "r"(a[1]), "r"(a[2]), "r"(a[3]), "r"(b0), "r"(b1));
}
__device__ __forceinline__ void cpa16(u32 d, const void* s) {
    asm volatile("cp.async.cg.shared.global [%0],[%1],16;" :: "r"(d), "l"(s));
}
__device__ __forceinline__ void cp_commit() {
    asm volatile("cp.async.commit_group;" ::: "memory");
}
template<int N> __device__ __forceinline__ void cp_wait() {
    asm volatile("cp.async.wait_group %0;" :: "n"(N) : "memory");
}
__device__ __forceinline__ void split2(float x0, float x1, u32& h, u32& l) {
    bf16 h0 = __float2bfloat16(x0);
    bf16 h1 = __float2bfloat16(x1);
    float r0 = x0 - __bfloat162float(h0);
    float r1 = x1 - __bfloat162float(h1);
    __nv_bfloat162 hp; hp.x = h0; hp.y = h1;
    __nv_bfloat162 lp; lp.x = __float2bfloat16(r0); lp.y = __float2bfloat16(r1);
    h = *reinterpret_cast<u32*>(&hp);
    l = *reinterpret_cast<u32*>(&lp);
}
__device__ __forceinline__ void split1(float x, bf16* hd, bf16* ld, size_t o) {
    bf16 h = __float2bfloat16(x);
    hd[o] = h;
    ld[o] = __float2bfloat16(x - __bfloat162float(h));
}

// ---------------- GEMM geometry ----------------------------------------------
#define APITCH 40
#define BPITCH 264
#define APB (64 * APITCH * 2)
#define BPB (32 * BPITCH * 2)
#define SMEM_BYTES (4 * APB + 4 * BPB)

// ---------------- generic bf16-split tensor-core GEMM -----------------------
template<bool DUAL>
__global__ void __launch_bounds__(256, 2) gemm_bf16(
    const bf16* __restrict__ Xh, const bf16* __restrict__ Xl,
    const bf16* __restrict__ Wh, const bf16* __restrict__ Wl,
    const float* __restrict__ bias, int IC, int NPIX,
    float* dstf, int dstf_stride,
    float* dstf2, int dst2_stride, int oc_split)
{
    extern __shared__ __align__(16) char sm[];
    const int tid = threadIdx.x;
    const int lane = tid & 31, warp = tid >> 5;
    const int px0 = blockIdx.x * 256;
    const int oc0 = blockIdx.y * 64;
    const int b   = blockIdx.z;
    const u32 smb = smem_u32(sm);

    const bf16* Xhb = Xh + (size_t)b * IC * NPIX;
    const bf16* Xlb = Xl + (size_t)b * IC * NPIX;

    const int ar = tid >> 2, ac = (tid & 3) * 8;
    const int bc = (tid & 31) * 8, br0 = tid >> 5;
    const int nk = IC >> 5;

    float c[4][4][4];
    #pragma unroll
    for (int i = 0; i < 4; i++)
        #pragma unroll
        for (int j = 0; j < 4; j++)
            #pragma unroll
            for (int q = 0; q < 4; q++) c[i][j][q] = 0.f;

    auto issue = [&](int it) {
        const int st = it & 1;
        const int k0 = it << 5;
        u32 aD = smb + st * 2 * APB + (u32)(ar * APITCH + ac) * 2;
        const size_t aO = (size_t)(oc0 + ar) * IC + k0 + ac;
        cpa16(aD, Wh + aO);
        cpa16(aD + APB, Wl + aO);
        const u32 bBase = smb + 4 * APB + st * 2 * BPB;
        #pragma unroll
        for (int i = 0; i < 4; i++) {
            const int brr = br0 + i * 8;
            u32 bD = bBase + (u32)(brr * BPITCH + bc) * 2;
            const size_t bO = (size_t)(k0 + brr) * NPIX + px0 + bc;
            cpa16(bD, Xhb + bO);
            cpa16(bD + BPB, Xlb + bO);
        }
        cp_commit();
    };

    issue(0);

    const int grp = lane >> 3, lr = lane & 7;
    const int r8  = (grp & 1) * 8 + lr;
    const int kh8 = (grp >> 1) * 8;
    const int wn32 = warp * 32;

    for (int it = 0; it < nk; it++) {
        if (it + 1 < nk) { issue(it + 1); cp_wait<1>(); }
        else             { cp_wait<0>(); }
        __syncthreads();
        const int st = it & 1;
        const u32 aHi = smb + st * 2 * APB, aLo = aHi + APB;
        const u32 bHi = smb + 4 * APB + st * 2 * BPB, bLo = bHi + BPB;
        #pragma unroll
        for (int ks = 0; ks < 2; ks++) {
            u32 bh[2][4], bl[2][4];
            #pragma unroll
            for (int g = 0; g < 2; g++) {
                const u32 off = (u32)((ks * 16 + r8) * BPITCH + wn32 + g * 16 + kh8) * 2;
                ldm_x4t(bHi + off, bh[g][0], bh[g][1], bh[g][2], bh[g][3]);
                ldm_x4t(bLo + off, bl[g][0], bl[g][1], bl[g][2], bl[g][3]);
            }
            #pragma unroll
            for (int mi = 0; mi < 4; mi++) {
                u32 ah[4], al[4];
                const u32 aoff = (u32)((mi * 16 + r8) * APITCH + ks * 16 + kh8) * 2;
                ldm_x4(aHi + aoff, ah[0], ah[1], ah[2], ah[3]);
                ldm_x4(aLo + aoff, al[0], al[1], al[2], al[3]);
                #pragma unroll
                for (int nj = 0; nj < 4; nj++) {
                    const int g = nj >> 1, s2 = nj & 1;
                    mma_bf16(c[mi][nj], ah, bh[g][2 * s2], bh[g][2 * s2 + 1]);
                    mma_bf16(c[mi][nj], ah, bl[g][2 * s2], bl[g][2 * s2 + 1]);
                    mma_bf16(c[mi][nj], al, bh[g][2 * s2], bh[g][2 * s2 + 1]);
                }
            }
        }
        __syncthreads();
    }

    // ---- epilogue
    const int r4 = lane >> 2, c2 = (lane & 3) * 2;
    #pragma unroll
    for (int mi = 0; mi < 4; mi++) {
        #pragma unroll
        for (int h = 0; h < 2; h++) {
            const int oc = oc0 + mi * 16 + h * 8 + r4;
            const float bv = bias[oc];
            #pragma unroll
            for (int nj = 0; nj < 4; nj++) {
                const int px = px0 + wn32 + nj * 8 + c2;
                const float v0 = c[mi][nj][h * 2]     + bv;
                const float v1 = c[mi][nj][h * 2 + 1] + bv;
                if (DUAL) {
                    if (oc < oc_split)
                        *reinterpret_cast<float2*>(dstf + (size_t)b * dstf_stride
                            + (size_t)oc * NPIX + px) = make_float2(v0, v1);
                    else
                        *reinterpret_cast<float2*>(dstf2 + (size_t)b * dst2_stride
                            + (size_t)(oc - oc_split) * NPIX + px) = make_float2(v0, v1);
                } else {
                    *reinterpret_cast<float2*>(dstf + (size_t)b * dstf_stride
                        + (size_t)oc * NPIX + px) = make_float2(v0, v1);
                }
            }
        }
    }
}

// ---------------- fused a1->swish->a2->tanh*v kernel -------------------------
// Phase 1: a = swish(Wa1 @ qk + ba1), a-tile kept in regs, split to smem.
// Phase 2: res_h = tanh((Wa2 @ a + ba2)*0.25) * v -> cat planes [0,64).
#define FAPITCH 72
#define FSTG (32 * BPITCH * 2)            // 16896 B per plane-half
#define FW1H (4 * FSTG)
#define FW1L (FW1H + 64 * FAPITCH * 2)
#define FW2H (FW1L + 64 * FAPITCH * 2)
#define FW2L (FW2H + 64 * FAPITCH * 2)
#define FSMEM (FW2L + 64 * FAPITCH * 2)   // 104448 B

__global__ void __launch_bounds__(256, 2) fused_a1a2(
    const bf16* __restrict__ qkh, const bf16* __restrict__ qkl,
    const float* __restrict__ ba1, const float* __restrict__ ba2,
    const float* __restrict__ vsrc,
    bf16* __restrict__ ch, bf16* __restrict__ cl)
{
    extern __shared__ __align__(16) char sm[];
    const int tid = threadIdx.x;
    const int lane = tid & 31, warp = tid >> 5;
    const int px0 = blockIdx.x * 256;
    const int b   = blockIdx.y;
    const u32 smb = smem_u32(sm);

    const bf16* qkhb = qkh + (size_t)b * 64 * HW + px0;
    const bf16* qklb = qkl + (size_t)b * 64 * HW + px0;

    // ---- W tiles: 4 planes of 64x64, pitch FAPITCH
    {
        const int r = tid >> 2;
        const int sb = (tid & 3) * 32;        // byte offset of 16-elem chunk
        const size_t go = (size_t)r * 64 + (tid & 3) * 16;
        const u32 so = (u32)(r * FAPITCH) * 2 + sb;
        cpa16(smb + FW1H + so, g_wa1h + go); cpa16(smb + FW1H + so + 16, g_wa1h + go + 8);
        cpa16(smb + FW1L + so, g_wa1l + go); cpa16(smb + FW1L + so + 16, g_wa1l + go + 8);
        cpa16(smb + FW2H + so, g_wa2h + go); cpa16(smb + FW2H + so + 16, g_wa2h + go + 8);
        cpa16(smb + FW2L + so, g_wa2l + go); cpa16(smb + FW2L + so + 16, g_wa2l + go + 8);
    }
    const int bc = (tid & 31) * 8, br0 = tid >> 5;
    auto issueB = [&](int chunk) {
        const u32 base = smb + chunk * 2 * FSTG;
        #pragma unroll
        for (int i = 0; i < 4; i++) {
            const int brr = br0 + i * 8;
            const u32 d = base + (u32)(brr * BPITCH + bc) * 2;
            const size_t o = (size_t)(chunk * 32 + brr) * HW + bc;
            cpa16(d, qkhb + o);
            cpa16(d + FSTG, qklb + o);
        }
        cp_commit();
    };
    issueB(0);
    issueB(1);

    const int grp = lane >> 3, lr = lane & 7;
    const int r8  = (grp & 1) * 8 + lr;
    const int kh8 = (grp >> 1) * 8;
    const int wn32 = warp * 32;
    const int r4 = lane >> 2, c2 = (lane & 3) * 2;

    float c[4][4][4];
    #pragma unroll
    for (int i = 0; i < 4; i++)
        #pragma unroll
        for (int j = 0; j < 4; j++)
            #pragma unroll
            for (int q = 0; q < 4; q++) c[i][j][q] = 0.f;

    // ---- phase 1
    for (int it = 0; it < 2; it++) {
        if (it == 0) cp_wait<1>(); else cp_wait<0>();
        __syncthreads();
        const u32 bHi = smb + it * 2 * FSTG, bLo = bHi + FSTG;
        #pragma unroll
        for (int ks = 0; ks < 2; ks++) {
            u32 bh[2][4], bl[2][4];
            #pragma unroll
            for (int g = 0; g < 2; g++) {
                const u32 off = (u32)((ks * 16 + r8) * BPITCH + wn32 + g * 16 + kh8) * 2;
                ldm_x4t(bHi + off, bh[g][0], bh[g][1], bh[g][2], bh[g][3]);
                ldm_x4t(bLo + off, bl[g][0], bl[g][1], bl[g][2], bl[g][3]);
            }
            #pragma unroll
            for (int mi = 0; mi < 4; mi++) {
                u32 ah[4], al[4];
                const u32 aoff = (u32)((mi * 16 + r8) * FAPITCH + it * 32 + ks * 16 + kh8) * 2;
                ldm_x4(smb + FW1H + aoff, ah[0], ah[1], ah[2], ah[3]);
                ldm_x4(smb + FW1L + aoff, al[0], al[1], al[2], al[3]);
                #pragma unroll
                for (int nj = 0; nj < 4; nj++) {
                    const int g = nj >> 1, s2 = nj & 1;
                    mma_bf16(c[mi][nj], ah, bh[g][2 * s2], bh[g][2 * s2 + 1]);
                    mma_bf16(c[mi][nj], ah, bl[g][2 * s2], bl[g][2 * s2 + 1]);
                    mma_bf16(c[mi][nj], al, bh[g][2 * s2], bh[g][2 * s2 + 1]);
                }
            }
        }
        __syncthreads();
    }

    // ---- swish + split a into smem (B layout: row = a-channel, col = px)
    #pragma unroll
    for (int mi = 0; mi < 4; mi++) {
        #pragma unroll
        for (int h = 0; h < 2; h++) {
            const int oc = mi * 16 + h * 8 + r4;
            const float bv = __ldg(&ba1[oc]);
            const u32 halfb = (oc & 32) ? 2u * FSTG : 0u;
            #pragma unroll
            for (int nj = 0; nj < 4; nj++) {
                float v0 = c[mi][nj][h * 2]     + bv;
                float v1 = c[mi][nj][h * 2 + 1] + bv;
                v0 = v0 / (1.f + __expf(-v0));
                v1 = v1 / (1.f + __expf(-v1));
                u32 hp, lp; split2(v0, v1, hp, lp);
                const u32 off = (u32)((oc & 31) * BPITCH + wn32 + nj * 8 + c2) * 2;
                *reinterpret_cast<u32*>(sm + halfb + off)        = hp;
                *reinterpret_cast<u32*>(sm + halfb + FSTG + off) = lp;
            }
        }
    }
    __syncthreads();

    // ---- phase 2
    #pragma unroll
    for (int i = 0; i < 4; i++)
        #pragma unroll
        for (int j = 0; j < 4; j++)
            #pragma unroll
            for (int q = 0; q < 4; q++) c[i][j][q] = 0.f;

    #pragma unroll
    for (int it = 0; it < 2; it++) {
        const u32 bHi = smb + it * 2 * FSTG, bLo = bHi + FSTG;
        #pragma unroll
        for (int ks = 0; ks < 2; ks++) {
            u32 bh[2][4], bl[2][4];
            #pragma unroll
            for (int g = 0; g < 2; g++) {
                const u32 off = (u32)((ks * 16 + r8) * BPITCH + wn32 + g * 16 + kh8) * 2;
                ldm_x4t(bHi + off, bh[g][0], bh[g][1], bh[g][2], bh[g][3]);
                ldm_x4t(bLo + off, bl[g][0], bl[g][1], bl[g][2], bl[g][3]);
            }
            #pragma unroll
            for (int mi = 0; mi < 4; mi++) {
                u32 ah[4], al[4];
                const u32 aoff = (u32)((mi * 16 + r8) * FAPITCH + it * 32 + ks * 16 + kh8) * 2;
                ldm_x4(smb + FW2H + aoff, ah[0], ah[1], ah[2], ah[3]);
                ldm_x4(smb + FW2L + aoff, al[0], al[1], al[2], al[3]);
                #pragma unroll
                for (int nj = 0; nj < 4; nj++) {
                    const int g = nj >> 1, s2 = nj & 1;
                    mma_bf16(c[mi][nj], ah, bh[g][2 * s2], bh[g][2 * s2 + 1]);
                    mma_bf16(c[mi][nj], ah, bl[g][2 * s2], bl[g][2 * s2 + 1]);
                    mma_bf16(c[mi][nj], al, bh[g][2 * s2], bh[g][2 * s2 + 1]);
                }
            }
        }
    }

    // ---- tanh*v epilogue -> cat hi/lo planes [0,64)
    #pragma unroll
    for (int mi = 0; mi < 4; mi++) {
        #pragma unroll
        for (int h = 0; h < 2; h++) {
            const int oc = mi * 16 + h * 8 + r4;
            const float bv = __ldg(&ba2[oc]);
            #pragma unroll
            for (int nj = 0; nj < 4; nj++) {
                const int px = px0 + wn32 + nj * 8 + c2;
                const float* vr = vsrc + ((size_t)b * 64 + oc) * HW + px;
                float v0 = tanhf((c[mi][nj][h * 2]     + bv) * 0.25f) * __ldg(vr);
                float v1 = tanhf((c[mi][nj][h * 2 + 1] + bv) * 0.25f) * __ldg(vr + 1);
                u32 hp, lp; split2(v0, v1, hp, lp);
                const size_t o = ((size_t)b * 128 + oc) * HW + px;
                *reinterpret_cast<u32*>(ch + o) = hp;
                *reinterpret_cast<u32*>(cl + o) = lp;
            }
        }
    }
}

// ---------------- weight prep ------------------------------------------------
__global__ void prep_weights(
    const float* __restrict__ Wqkv, const float* __restrict__ Wq,
    const float* __restrict__ Wa1, const float* __restrict__ Wa2,
    const float* __restrict__ Wproj,
    const float* __restrict__ bqkv, const float* __restrict__ bq)
{
    const int i = blockIdx.x * 256 + threadIdx.x;
    if (i < 32768) {
        float v = (i < 24576) ? Wqkv[i] : Wq[i - 24576];
        split1(v, g_w1h, g_w1l, i);
    } else if (i < 36864) {
        split1(Wa1[i - 32768], g_wa1h, g_wa1l, i - 32768);
    } else if (i < 40960) {
        split1(Wa2[i - 36864], g_wa2h, g_wa2l, i - 36864);
    } else if (i < 57344) {
        split1(Wproj[i - 40960], g_wph, g_wpl, i - 40960);
    } else if (i < 57600) {
        const int j = i - 57344;
        g_b1[j] = (j < 192) ? bqkv[j] : bq[j - 192];
    }
}

// ---------------- x -> hi/lo bf16 + 8x8 avgpool (one pass) -------------------
__global__ void __launch_bounds__(256) cvtpool(
    const float* __restrict__ x, bf16* __restrict__ xh, bf16* __restrict__ xl,
    float* __restrict__ xp)
{
    const int plane = blockIdx.x;            // b*128 + c
    const int t = threadIdx.x;               // one 8x8 window per thread
    const int wi = t >> 4, wj = t & 15;
    const float* sp = x + (size_t)plane * HW + (wi * 8) * WW + wj * 8;
    bf16* oh = xh + (size_t)plane * HW + (wi * 8) * WW + wj * 8;
    bf16* ol = xl + (size_t)plane * HW + (wi * 8) * WW + wj * 8;

    float s = 0.f;
    #pragma unroll
    for (int r = 0; r < 8; r++) {
        const float4 a = *reinterpret_cast<const float4*>(sp + r * WW);
        const float4 b = *reinterpret_cast<const float4*>(sp + r * WW + 4);
        s += a.x + a.y + a.z + a.w + b.x + b.y + b.z + b.w;
        u32 h0, l0, h1, l1, h2, l2, h3, l3;
        split2(a.x, a.y, h0, l0); split2(a.z, a.w, h1, l1);
        split2(b.x, b.y, h2, l2); split2(b.z, b.w, h3, l3);
        *reinterpret_cast<uint4*>(oh + r * WW) = make_uint4(h0, h1, h2, h3);
        *reinterpret_cast<uint4*>(ol + r * WW) = make_uint4(l0, l1, l2, l3);
    }
    xp[(size_t)plane * 256 + wi * 16 + wj] = s * (1.f / 64.f);
}

// ---------------- depthwise 3x3, smem-tiled rolling stencil -----------------
__global__ void __launch_bounds__(128) dwconv_qk(
    const float* __restrict__ qkv, const float* __restrict__ w,
    const float* __restrict__ bias,
    bf16* __restrict__ qkh, bf16* __restrict__ qkl,
    float* __restrict__ vout)
{
    const int z = blockIdx.z;
    const int b = z >> 7, t = z & 127;
    const int x = threadIdx.x;
    const int y0 = blockIdx.y * 16;

    __shared__ float s0[18][136];
    __shared__ float s1[18][136];

    if (t < 64) {
        const float* pq = qkv + ((size_t)b * 192 + t) * HW;
        const float* pk = qkv + ((size_t)b * 192 + 64 + t) * HW;
        #pragma unroll
        for (int r = 0; r < 18; r++) {
            const int yy = y0 - 1 + r;
            const bool ok = (yy >= 0) && (yy < HH);
            s0[r][x + 1] = ok ? __ldg(pq + yy * WW + x) : 0.f;
            s1[r][x + 1] = ok ? __ldg(pk + yy * WW + x) : 0.f;
        }
        if (x < 2) {
            const int col = x ? 129 : 0;
            #pragma unroll
            for (int r = 0; r < 18; r++) { s0[r][col] = 0.f; s1[r][col] = 0.f; }
        }
        __syncthreads();

        float wq[9], wk[9];
        #pragma unroll
        for (int i = 0; i < 9; i++) {
            wq[i] = __ldg(&w[t * 9 + i]);
            wk[i] = __ldg(&w[(64 + t) * 9 + i]);
        }
        const float bq = __ldg(&bias[t]);
        const float bk = __ldg(&bias[64 + t]);

        bf16* oh = qkh + ((size_t)b * 64 + t) * HW + (size_t)y0 * WW + x;
        bf16* ol = qkl + ((size_t)b * 64 + t) * HW + (size_t)y0 * WW + x;

        float Aq = 0.f, Bq = 0.f, Ak = 0.f, Bk = 0.f;
        #pragma unroll
        for (int r = 0; r < 18; r++) {
            const float lq = s0[r][x], cq = s0[r][x + 1], rq = s0[r][x + 2];
            const float h0q = wq[0]*lq + wq[1]*cq + wq[2]*rq;
            const float h1q = wq[3]*lq + wq[4]*cq + wq[5]*rq;
            const float h2q = wq[6]*lq + wq[7]*cq + wq[8]*rq;
            const float lk = s1[r][x], ck = s1[r][x + 1], rk = s1[r][x + 2];
            const float h0k = wk[0]*lk + wk[1]*ck + wk[2]*rk;
            const float h1k = wk[3]*lk + wk[4]*ck + wk[5]*rk;
            const float h2k = wk[6]*lk + wk[7]*ck + wk[8]*rk;
            Aq += h2q; Ak += h2k;
            if (r >= 2) {
                const int o = r - 2;
                const float prod = (Aq + bq) * (Ak + bk);
                const bf16 hv = __float2bfloat16(prod);
                oh[o * WW] = hv;
                ol[o * WW] = __float2bfloat16(prod - __bfloat162float(hv));
            }
            Aq = Bq + h1q; Bq = h0q;
            Ak = Bk + h1k; Bk = h0k;
        }
    } else {
        const int cv = t - 64;
        const float* pv = qkv + ((size_t)b * 192 + 128 + cv) * HW;
        #pragma unroll
        for (int r = 0; r < 18; r++) {
            const int yy = y0 - 1 + r;
            s0[r][x + 1] = (yy >= 0 && yy < HH) ? __ldg(pv + yy * WW + x) : 0.f;
        }
        if (x < 2) {
            const int col = x ? 129 : 0;
            #pragma unroll
            for (int r = 0; r < 18; r++) s0[r][col] = 0.f;
        }
        __syncthreads();

        float wv[9];
        #pragma unroll
        for (int i = 0; i < 9; i++) wv[i] = __ldg(&w[(128 + cv) * 9 + i]);
        const float bv = __ldg(&bias[128 + cv]);

        float* ov = vout + ((size_t)b * 64 + cv) * HW + (size_t)y0 * WW + x;
        float A = 0.f, Bv = 0.f;
        #pragma unroll
        for (int r = 0; r < 18; r++) {
            const float lv = s0[r][x], cvv = s0[r][x + 1], rv = s0[r][x + 2];
            const float h0 = wv[0]*lv + wv[1]*cvv + wv[2]*rv;
            const float h1 = wv[3]*lv + wv[4]*cvv + wv[5]*rv;
            const float h2 = wv[6]*lv + wv[7]*cvv + wv[8]*rv;
            A += h2;
            if (r >= 2) ov[(r - 2) * WW] = A + bv;
            A = Bv + h1; Bv = h0;
        }
    }
}

// ---------------- kv = Wkv @ xp + bkv (SIMT, fp32) ---------------------------
__global__ void __launch_bounds__(256) kv_simt(
    const float* __restrict__ xp, const float* __restrict__ Wkv,
    const float* __restrict__ bkv, float* __restrict__ kvout)
{
    const int idx = blockIdx.x * 256 + threadIdx.x;
    const int p  = idx & 255;
    const int oc = (idx >> 8) & 127;
    const int b  = idx >> 15;
    const float* xpb = xp + (size_t)b * 128 * 256 + p;
    const float* wr  = Wkv + oc * 128;
    float acc = __ldg(&bkv[oc]);
    #pragma unroll 8
    for (int c = 0; c < 128; c++)
        acc += __ldg(wr + c) * __ldg(xpb + c * 256);
    kvout[((size_t)b * 128 + oc) * 256 + p] = acc;
}

// ---------------- low-freq softmax attention (2 px/thread) -------------------
__global__ void __launch_bounds__(128) lowfreq_attn(
    const float* __restrict__ qg, const float* __restrict__ kv,
    bf16* __restrict__ ch, bf16* __restrict__ cl)
{
    const int b = blockIdx.z, h = blockIdx.y;
    const int p = blockIdx.x * 256 + threadIdx.x;

    __shared__ __align__(16) u64 ks2[256][8];
    __shared__ __align__(16) u64 vs2[256][8];

    const float* kvb = kv + (size_t)b * 128 * 256;
    for (int i = threadIdx.x; i < 2048; i += 128) {
        const int d2 = i >> 8, m = i & 255;
        ks2[m][d2] = pack2(kvb[(h * 16 + 2 * d2) * 256 + m],
                           kvb[(h * 16 + 2 * d2 + 1) * 256 + m]);
        vs2[m][d2] = pack2(kvb[(64 + h * 16 + 2 * d2) * 256 + m],
                           kvb[(64 + h * 16 + 2 * d2 + 1) * 256 + m]);
    }
    __syncthreads();

    u64 qa[8], qb[8];
    #pragma unroll
    for (int d2 = 0; d2 < 8; d2++) {
        const size_t base = (size_t)b * 64 * HW + (size_t)(h * 16 + 2 * d2) * HW + p;
        qa[d2] = pack2(0.25f * __ldg(&qg[base]),       0.25f * __ldg(&qg[base + HW]));
        qb[d2] = pack2(0.25f * __ldg(&qg[base + 128]), 0.25f * __ldg(&qg[base + HW + 128]));
    }

    float suma = 0.f, sumb = 0.f;
    u64 acca[8], accb[8];
    #pragma unroll
    for (int d2 = 0; d2 < 8; d2++) { acca[d2] = 0ull; accb[d2] = 0ull; }

    for (int m = 0; m < 256; m++) {
        u64 sa = 0ull, sb = 0ull;
        #pragma unroll
        for (int d2 = 0; d2 < 8; d2++) {
            const u64 kk = ks2[m][d2];
            sa = ffma2(qa[d2], kk, sa);
            sb = ffma2(qb[d2], kk, sb);
        }
        float a0, a1, b0, b1;
        unpack2(sa, a0, a1); unpack2(sb, b0, b1);
        const float ea = __expf(a0 + a1);
        const float eb = __expf(b0 + b1);
        suma += ea; sumb += eb;
        const u64 ea2 = pack2(ea, ea), eb2 = pack2(eb, eb);
        #pragma unroll
        for (int d2 = 0; d2 < 8; d2++) {
            const u64 vv = vs2[m][d2];
            acca[d2] = ffma2(ea2, vv, acca[d2]);
            accb[d2] = ffma2(eb2, vv, accb[d2]);
        }
    }

    const float inva = 1.f / suma, invb = 1.f / sumb;
    #pragma unroll
    for (int d2 = 0; d2 < 8; d2++) {
        float lo, hi;
        unpack2(acca[d2], lo, hi);
        const size_t base = ((size_t)b * 128 + 64 + h * 16 + 2 * d2) * HW + p;
        split1(lo * inva, ch, cl, base);
        split1(hi * inva, ch, cl, base + HW);
        unpack2(accb[d2], lo, hi);
        split1(lo * invb, ch, cl, base + 128);
        split1(hi * invb, ch, cl, base + HW + 128);
    }
}

// ---------------- launch -----------------------------------------------------
extern "C" void kernel_launch(void* const* d_in, const int* in_sizes, int n_in,
                              void* d_out, int out_size)
{
    const float* x     = (const float*)d_in[0];
    const float* Wqkv  = (const float*)d_in[1];
    const float* bqkv  = (const float*)d_in[2];
    const float* Wdw   = (const float*)d_in[3];
    const float* bdw   = (const float*)d_in[4];
    const float* Wa1   = (const float*)d_in[5];
    const float* ba1   = (const float*)d_in[6];
    const float* Wa2   = (const float*)d_in[7];
    const float* ba2   = (const float*)d_in[8];
    const float* Wq    = (const float*)d_in[9];
    const float* bq    = (const float*)d_in[10];
    const float* Wkv   = (const float*)d_in[11];
    const float* bkv   = (const float*)d_in[12];
    const float* Wproj = (const float*)d_in[13];
    const float* bproj = (const float*)d_in[14];
    float* out = (float*)d_out;

    float *qkv, *v, *qg, *kv, *xp, *b1;
    bf16 *xh, *xl, *qkh, *qkl, *ch, *cl;
    bf16 *w1h, *w1l, *wph, *wpl;
    cudaGetSymbolAddress((void**)&qkv, g_qkv);
    cudaGetSymbolAddress((void**)&v,   g_v);
    cudaGetSymbolAddress((void**)&qg,  g_qg);
    cudaGetSymbolAddress((void**)&kv,  g_kv);
    cudaGetSymbolAddress((void**)&xp,  g_xp);
    cudaGetSymbolAddress((void**)&b1,  g_b1);
    cudaGetSymbolAddress((void**)&xh,  g_xh);
    cudaGetSymbolAddress((void**)&xl,  g_xl);
    cudaGetSymbolAddress((void**)&qkh, g_qkh);
    cudaGetSymbolAddress((void**)&qkl, g_qkl);
    cudaGetSymbolAddress((void**)&ch,  g_ch);
    cudaGetSymbolAddress((void**)&cl,  g_cl);
    cudaGetSymbolAddress((void**)&w1h, g_w1h);
    cudaGetSymbolAddress((void**)&w1l, g_w1l);
    cudaGetSymbolAddress((void**)&wph, g_wph);
    cudaGetSymbolAddress((void**)&wpl, g_wpl);

    cudaFuncSetAttribute(gemm_bf16<true>,
                         cudaFuncAttributeMaxDynamicSharedMemorySize, SMEM_BYTES);
    cudaFuncSetAttribute(gemm_bf16<false>,
                         cudaFuncAttributeMaxDynamicSharedMemorySize, SMEM_BYTES);
    cudaFuncSetAttribute(fused_a1a2,
                         cudaFuncAttributeMaxDynamicSharedMemorySize, FSMEM);

    // 0) weight prep + x split/pool
    prep_weights<<<225, 256>>>(Wqkv, Wq, Wa1, Wa2, Wproj, bqkv, bq);
    cvtpool<<<NB * 128, 256>>>(x, xh, xl, xp);

    // 1) fused qkv+qg GEMM
    gemm_bf16<true><<<dim3(HW / 256, 4, NB), 256, SMEM_BYTES>>>(
        xh, xl, w1h, w1l, b1, 128, HW,
        qkv, 192 * HW, qg, 64 * HW, 192);

    // 2) depthwise 3x3 with q*k fusion
    dwconv_qk<<<dim3(1, 8, NB * 128), 128>>>(qkv, Wdw, bdw, qkh, qkl, v);

    // 3+4) fused a1 -> swish -> a2 -> tanh*v  -> cat planes [0,64)
    fused_a1a2<<<dim3(HW / 256, NB), 256, FSMEM>>>(qkh, qkl, ba1, ba2, v, ch, cl);

    // 5) kv = Wkv @ xp (SIMT)
    kv_simt<<<NB * 128 * 256 / 256, 256>>>(xp, Wkv, bkv, kv);

    // 6) low-freq attention -> cat planes [64,128)
    lowfreq_attn<<<dim3(HW / 256, 4, NB), 128>>>(qg, kv, ch, cl);

    // 7) out = Wproj @ cat
    gemm_bf16<false><<<dim3(HW / 256, 2, NB), 256, SMEM_BYTES>>>(
        ch, cl, wph, wpl, bproj, 128, HW,
        out, 128 * HW, nullptr, 0, 0);
}

// round 8
// speedup vs baseline: 2.3190x; 1.0983x over previous
#include <cuda_runtime.h>
#include <cuda_bf16.h>
#include <math.h>

#define HW 16384
#define HH 128
#define WW 128
#define NB 4

typedef unsigned long long u64;
typedef unsigned int u32;
typedef __nv_bfloat16 bf16;

// ---------------- f32x2 helpers (attention) ---------------------------------
__device__ __forceinline__ u64 pack2(float lo, float hi) {
    u64 r; asm("mov.b64 %0,{%1,%2};" : "=l"(r) : "f"(lo), "f"(hi)); return r;
}
__device__ __forceinline__ void unpack2(u64 v, float& lo, float& hi) {
    asm("mov.b64 {%0,%1},%2;" : "=f"(lo), "=f"(hi) : "l"(v));
}
__device__ __forceinline__ u64 ffma2(u64 a, u64 b, u64 c) {
    u64 r; asm("fma.rn.f32x2 %0,%1,%2,%3;" : "=l"(r) : "l"(a), "l"(b), "l"(c)); return r;
}

// ---------------- scratch ----------------------------------------------------
__device__ __align__(256) float g_qkv [NB * 192 * HW];
__device__ __align__(256) float g_v   [NB * 64  * HW];
__device__ __align__(256) float g_qg  [NB * 64  * HW];
__device__ __align__(256) float g_kv  [NB * 128 * 256];
__device__ __align__(256) float g_xp  [NB * 128 * 256];
__device__ __align__(256) bf16  g_xh  [NB * 128 * HW];
__device__ __align__(256) bf16  g_xl  [NB * 128 * HW];
__device__ __align__(256) bf16  g_qkh [NB * 64 * HW];
__device__ __align__(256) bf16  g_qkl [NB * 64 * HW];
__device__ __align__(256) bf16  g_ch  [NB * 128 * HW];
__device__ __align__(256) bf16  g_cl  [NB * 128 * HW];
__device__ __align__(256) bf16  g_w1h [256 * 128];
__device__ __align__(256) bf16  g_w1l [256 * 128];
__device__ __align__(256) bf16  g_wa1h[64 * 64];
__device__ __align__(256) bf16  g_wa1l[64 * 64];
__device__ __align__(256) bf16  g_wa2h[64 * 64];
__device__ __align__(256) bf16  g_wa2l[64 * 64];
__device__ __align__(256) bf16  g_wph [128 * 128];
__device__ __align__(256) bf16  g_wpl [128 * 128];
__device__ __align__(256) float g_b1  [256];

// ---------------- mma / cp.async helpers ------------------------------------
__device__ __forceinline__ u32 smem_u32(const void* p) {
    u32 a;
    asm("{ .reg .u64 t; cvta.to.shared.u64 t, %1; cvt.u32.u64 %0, t; }"
        : "=r"(a) : "l"(p));
    return a;
}
__device__ __forceinline__ void ldm_x4(u32 a, u32& r0, u32& r1, u32& r2, u32& r3) {
    asm volatile("ldmatrix.sync.aligned.m8n8.x4.shared.b16 {%0,%1,%2,%3},[%4];"
                 : "=r"(r0), "=r"(r1), "=r"(r2), "=r"(r3) : "r"(a));
}
__device__ __forceinline__ void ldm_x4t(u32 a, u32& r0, u32& r1, u32& r2, u32& r3) {
    asm volatile("ldmatrix.sync.aligned.m8n8.x4.trans.shared.b16 {%0,%1,%2,%3},[%4];"
                 : "=r"(r0), "=r"(r1), "=r"(r2), "=r"(r3) : "r"(a));
}
__device__ __forceinline__ void mma_bf16(float* c, const u32* a, u32 b0, u32 b1) {
    asm volatile(
        "mma.sync.aligned.m16n8k16.row.col.f32.bf16.bf16.f32 "
        "{%0,%1,%2,%3},{%4,%5,%6,%7},{%8,%9},{%0,%1,%2,%3};"
        : "+f"(c[0]), "+f"(c[1]), "+f"(c[2]), "+f"(c[3])
        : "r"(a[0]), "r"(a[1]), "r"(a[2]), "r"(a[3]), "r"(b0), "r"(b1));
}
__device__ __forceinline__ void cpa16(u32 d, const void* s) {
    asm volatile("cp.async.cg.shared.global [%0],[%1],16;" :: "r"(d), "l"(s));
}
__device__ __forceinline__ void cp_commit() {
    asm volatile("cp.async.commit_group;" ::: "memory");
}
template<int N> __device__ __forceinline__ void cp_wait() {
    asm volatile("cp.async.wait_group %0;" :: "n"(N) : "memory");
}
__device__ __forceinline__ void split2(float x0, float x1, u32& h, u32& l) {
    bf16 h0 = __float2bfloat16(x0);
    bf16 h1 = __float2bfloat16(x1);
    float r0 = x0 - __bfloat162float(h0);
    float r1 = x1 - __bfloat162float(h1);
    __nv_bfloat162 hp; hp.x = h0; hp.y = h1;
    __nv_bfloat162 lp; lp.x = __float2bfloat16(r0); lp.y = __float2bfloat16(r1);
    h = *reinterpret_cast<u32*>(&hp);
    l = *reinterpret_cast<u32*>(&lp);
}
__device__ __forceinline__ void split1(float x, bf16* hd, bf16* ld, size_t o) {
    bf16 h = __float2bfloat16(x);
    hd[o] = h;
    ld[o] = __float2bfloat16(x - __bfloat162float(h));
}

// ---------------- GEMM geometry ----------------------------------------------
#define APITCH 40
#define BPITCH 264
#define APB (64 * APITCH * 2)
#define BPB (32 * BPITCH * 2)
#define SMEM_BYTES (4 * APB + 4 * BPB)

// ---------------- generic bf16-split tensor-core GEMM -----------------------
template<bool DUAL>
__global__ void __launch_bounds__(256, 2) gemm_bf16(
    const bf16* __restrict__ Xh, const bf16* __restrict__ Xl,
    const bf16* __restrict__ Wh, const bf16* __restrict__ Wl,
    const float* __restrict__ bias, int IC, int NPIX,
    float* dstf, int dstf_stride,
    float* dstf2, int dst2_stride, int oc_split)
{
    extern __shared__ __align__(16) char sm[];
    const int tid = threadIdx.x;
    const int lane = tid & 31, warp = tid >> 5;
    const int px0 = blockIdx.x * 256;
    const int oc0 = blockIdx.y * 64;
    const int b   = blockIdx.z;
    const u32 smb = smem_u32(sm);

    const bf16* Xhb = Xh + (size_t)b * IC * NPIX;
    const bf16* Xlb = Xl + (size_t)b * IC * NPIX;

    const int ar = tid >> 2, ac = (tid & 3) * 8;
    const int bc = (tid & 31) * 8, br0 = tid >> 5;
    const int nk = IC >> 5;

    float c[4][4][4];
    #pragma unroll
    for (int i = 0; i < 4; i++)
        #pragma unroll
        for (int j = 0; j < 4; j++)
            #pragma unroll
            for (int q = 0; q < 4; q++) c[i][j][q] = 0.f;

    auto issue = [&](int it) {
        const int st = it & 1;
        const int k0 = it << 5;
        u32 aD = smb + st * 2 * APB + (u32)(ar * APITCH + ac) * 2;
        const size_t aO = (size_t)(oc0 + ar) * IC + k0 + ac;
        cpa16(aD, Wh + aO);
        cpa16(aD + APB, Wl + aO);
        const u32 bBase = smb + 4 * APB + st * 2 * BPB;
        #pragma unroll
        for (int i = 0; i < 4; i++) {
            const int brr = br0 + i * 8;
            u32 bD = bBase + (u32)(brr * BPITCH + bc) * 2;
            const size_t bO = (size_t)(k0 + brr) * NPIX + px0 + bc;
            cpa16(bD, Xhb + bO);
            cpa16(bD + BPB, Xlb + bO);
        }
        cp_commit();
    };

    issue(0);

    const int grp = lane >> 3, lr = lane & 7;
    const int r8  = (grp & 1) * 8 + lr;
    const int kh8 = (grp >> 1) * 8;
    const int wn32 = warp * 32;

    for (int it = 0; it < nk; it++) {
        if (it + 1 < nk) { issue(it + 1); cp_wait<1>(); }
        else             { cp_wait<0>(); }
        __syncthreads();
        const int st = it & 1;
        const u32 aHi = smb + st * 2 * APB, aLo = aHi + APB;
        const u32 bHi = smb + 4 * APB + st * 2 * BPB, bLo = bHi + BPB;
        #pragma unroll
        for (int ks = 0; ks < 2; ks++) {
            u32 bh[2][4], bl[2][4];
            #pragma unroll
            for (int g = 0; g < 2; g++) {
                const u32 off = (u32)((ks * 16 + r8) * BPITCH + wn32 + g * 16 + kh8) * 2;
                ldm_x4t(bHi + off, bh[g][0], bh[g][1], bh[g][2], bh[g][3]);
                ldm_x4t(bLo + off, bl[g][0], bl[g][1], bl[g][2], bl[g][3]);
            }
            #pragma unroll
            for (int mi = 0; mi < 4; mi++) {
                u32 ah[4], al[4];
                const u32 aoff = (u32)((mi * 16 + r8) * APITCH + ks * 16 + kh8) * 2;
                ldm_x4(aHi + aoff, ah[0], ah[1], ah[2], ah[3]);
                ldm_x4(aLo + aoff, al[0], al[1], al[2], al[3]);
                #pragma unroll
                for (int nj = 0; nj < 4; nj++) {
                    const int g = nj >> 1, s2 = nj & 1;
                    mma_bf16(c[mi][nj], ah, bh[g][2 * s2], bh[g][2 * s2 + 1]);
                    mma_bf16(c[mi][nj], ah, bl[g][2 * s2], bl[g][2 * s2 + 1]);
                    mma_bf16(c[mi][nj], al, bh[g][2 * s2], bh[g][2 * s2 + 1]);
                }
            }
        }
        __syncthreads();
    }

    // ---- epilogue
    const int r4 = lane >> 2, c2 = (lane & 3) * 2;
    #pragma unroll
    for (int mi = 0; mi < 4; mi++) {
        #pragma unroll
        for (int h = 0; h < 2; h++) {
            const int oc = oc0 + mi * 16 + h * 8 + r4;
            const float bv = bias[oc];
            #pragma unroll
            for (int nj = 0; nj < 4; nj++) {
                const int px = px0 + wn32 + nj * 8 + c2;
                const float v0 = c[mi][nj][h * 2]     + bv;
                const float v1 = c[mi][nj][h * 2 + 1] + bv;
                if (DUAL) {
                    if (oc < oc_split)
                        *reinterpret_cast<float2*>(dstf + (size_t)b * dstf_stride
                            + (size_t)oc * NPIX + px) = make_float2(v0, v1);
                    else
                        *reinterpret_cast<float2*>(dstf2 + (size_t)b * dst2_stride
                            + (size_t)(oc - oc_split) * NPIX + px) = make_float2(v0, v1);
                } else {
                    *reinterpret_cast<float2*>(dstf + (size_t)b * dstf_stride
                        + (size_t)oc * NPIX + px) = make_float2(v0, v1);
                }
            }
        }
    }
}

// ---------------- fused a1->swish->a2->tanh*v, 128-px tiles -----------------
#define F2PITCH 136
#define F2STG (32 * F2PITCH * 2)            // 8704 B per plane-half
#define F2W1H (4 * F2STG)                   // 34816
#define F2W1L (F2W1H + 64 * 72 * 2)
#define F2W2H (F2W1L + 64 * 72 * 2)
#define F2W2L (F2W2H + 64 * 72 * 2)
#define F2SMEM (F2W2L + 64 * 72 * 2)        // 71680 B

__global__ void __launch_bounds__(256, 3) fused_a1a2(
    const bf16* __restrict__ qkh, const bf16* __restrict__ qkl,
    const float* __restrict__ ba1, const float* __restrict__ ba2,
    const float* __restrict__ vsrc,
    bf16* __restrict__ ch, bf16* __restrict__ cl)
{
    extern __shared__ __align__(16) char sm[];
    const int tid = threadIdx.x;
    const int lane = tid & 31, warp = tid >> 5;
    const int px0 = blockIdx.x * 128;
    const int b   = blockIdx.y;
    const u32 smb = smem_u32(sm);

    const bf16* qkhb = qkh + (size_t)b * 64 * HW + px0;
    const bf16* qklb = qkl + (size_t)b * 64 * HW + px0;

    // weights: 4 planes of 64x64, pitch 72
    {
        const int r = tid >> 2;
        const int sb = (tid & 3) * 32;
        const size_t go = (size_t)r * 64 + (tid & 3) * 16;
        const u32 so = (u32)(r * 72) * 2 + sb;
        cpa16(smb + F2W1H + so, g_wa1h + go); cpa16(smb + F2W1H + so + 16, g_wa1h + go + 8);
        cpa16(smb + F2W1L + so, g_wa1l + go); cpa16(smb + F2W1L + so + 16, g_wa1l + go + 8);
        cpa16(smb + F2W2H + so, g_wa2h + go); cpa16(smb + F2W2H + so + 16, g_wa2h + go + 8);
        cpa16(smb + F2W2L + so, g_wa2l + go); cpa16(smb + F2W2L + so + 16, g_wa2l + go + 8);
    }
    const int bc = (tid & 15) * 8, br0 = tid >> 4;
    auto issueB = [&](int chunk) {
        const u32 base = smb + chunk * 2 * F2STG;
        #pragma unroll
        for (int i = 0; i < 2; i++) {
            const int brr = br0 + i * 16;
            const u32 d = base + (u32)(brr * F2PITCH + bc) * 2;
            const size_t o = (size_t)(chunk * 32 + brr) * HW + bc;
            cpa16(d, qkhb + o);
            cpa16(d + F2STG, qklb + o);
        }
        cp_commit();
    };
    issueB(0);
    issueB(1);

    const int grp = lane >> 3, lr = lane & 7;
    const int r8  = (grp & 1) * 8 + lr;
    const int kh8 = (grp >> 1) * 8;
    const int wn16 = warp * 16;
    const int r4 = lane >> 2, c2 = (lane & 3) * 2;

    float c[4][2][4];
    #pragma unroll
    for (int i = 0; i < 4; i++)
        #pragma unroll
        for (int j = 0; j < 2; j++)
            #pragma unroll
            for (int q = 0; q < 4; q++) c[i][j][q] = 0.f;

    // ---- phase 1
    for (int it = 0; it < 2; it++) {
        if (it == 0) cp_wait<1>(); else cp_wait<0>();
        __syncthreads();
        const u32 bHi = smb + it * 2 * F2STG, bLo = bHi + F2STG;
        #pragma unroll
        for (int ks = 0; ks < 2; ks++) {
            u32 bh[4], bl[4];
            const u32 off = (u32)((ks * 16 + r8) * F2PITCH + wn16 + kh8) * 2;
            ldm_x4t(bHi + off, bh[0], bh[1], bh[2], bh[3]);
            ldm_x4t(bLo + off, bl[0], bl[1], bl[2], bl[3]);
            #pragma unroll
            for (int mi = 0; mi < 4; mi++) {
                u32 ah[4], al[4];
                const u32 aoff = (u32)((mi * 16 + r8) * 72 + it * 32 + ks * 16 + kh8) * 2;
                ldm_x4(smb + F2W1H + aoff, ah[0], ah[1], ah[2], ah[3]);
                ldm_x4(smb + F2W1L + aoff, al[0], al[1], al[2], al[3]);
                #pragma unroll
                for (int nj = 0; nj < 2; nj++) {
                    mma_bf16(c[mi][nj], ah, bh[2 * nj], bh[2 * nj + 1]);
                    mma_bf16(c[mi][nj], ah, bl[2 * nj], bl[2 * nj + 1]);
                    mma_bf16(c[mi][nj], al, bh[2 * nj], bh[2 * nj + 1]);
                }
            }
        }
    }
    __syncthreads();

    // ---- swish + split a into smem (row = a-channel, col = px)
    #pragma unroll
    for (int mi = 0; mi < 4; mi++) {
        #pragma unroll
        for (int h = 0; h < 2; h++) {
            const int oc = mi * 16 + h * 8 + r4;
            const float bv = __ldg(&ba1[oc]);
            const u32 halfb = (oc & 32) ? 2u * F2STG : 0u;
            #pragma unroll
            for (int nj = 0; nj < 2; nj++) {
                float v0 = c[mi][nj][h * 2]     + bv;
                float v1 = c[mi][nj][h * 2 + 1] + bv;
                v0 = v0 / (1.f + __expf(-v0));
                v1 = v1 / (1.f + __expf(-v1));
                u32 hp, lp; split2(v0, v1, hp, lp);
                const u32 off = (u32)((oc & 31) * F2PITCH + wn16 + nj * 8 + c2) * 2;
                *reinterpret_cast<u32*>(sm + halfb + off)         = hp;
                *reinterpret_cast<u32*>(sm + halfb + F2STG + off) = lp;
            }
        }
    }
    __syncthreads();

    // ---- phase 2
    #pragma unroll
    for (int i = 0; i < 4; i++)
        #pragma unroll
        for (int j = 0; j < 2; j++)
            #pragma unroll
            for (int q = 0; q < 4; q++) c[i][j][q] = 0.f;

    #pragma unroll
    for (int it = 0; it < 2; it++) {
        const u32 bHi = smb + it * 2 * F2STG, bLo = bHi + F2STG;
        #pragma unroll
        for (int ks = 0; ks < 2; ks++) {
            u32 bh[4], bl[4];
            const u32 off = (u32)((ks * 16 + r8) * F2PITCH + wn16 + kh8) * 2;
            ldm_x4t(bHi + off, bh[0], bh[1], bh[2], bh[3]);
            ldm_x4t(bLo + off, bl[0], bl[1], bl[2], bl[3]);
            #pragma unroll
            for (int mi = 0; mi < 4; mi++) {
                u32 ah[4], al[4];
                const u32 aoff = (u32)((mi * 16 + r8) * 72 + it * 32 + ks * 16 + kh8) * 2;
                ldm_x4(smb + F2W2H + aoff, ah[0], ah[1], ah[2], ah[3]);
                ldm_x4(smb + F2W2L + aoff, al[0], al[1], al[2], al[3]);
                #pragma unroll
                for (int nj = 0; nj < 2; nj++) {
                    mma_bf16(c[mi][nj], ah, bh[2 * nj], bh[2 * nj + 1]);
                    mma_bf16(c[mi][nj], ah, bl[2 * nj], bl[2 * nj + 1]);
                    mma_bf16(c[mi][nj], al, bh[2 * nj], bh[2 * nj + 1]);
                }
            }
        }
    }

    // ---- tanh*v epilogue -> cat hi/lo planes [0,64)
    #pragma unroll
    for (int mi = 0; mi < 4; mi++) {
        #pragma unroll
        for (int h = 0; h < 2; h++) {
            const int oc = mi * 16 + h * 8 + r4;
            const float bv = __ldg(&ba2[oc]);
            #pragma unroll
            for (int nj = 0; nj < 2; nj++) {
                const int px = px0 + wn16 + nj * 8 + c2;
                const float* vr = vsrc + ((size_t)b * 64 + oc) * HW + px;
                float v0 = tanhf((c[mi][nj][h * 2]     + bv) * 0.25f) * __ldg(vr);
                float v1 = tanhf((c[mi][nj][h * 2 + 1] + bv) * 0.25f) * __ldg(vr + 1);
                u32 hp, lp; split2(v0, v1, hp, lp);
                const size_t o = ((size_t)b * 128 + oc) * HW + px;
                *reinterpret_cast<u32*>(ch + o) = hp;
                *reinterpret_cast<u32*>(cl + o) = lp;
            }
        }
    }
}

// ---------------- weight prep ------------------------------------------------
__global__ void prep_weights(
    const float* __restrict__ Wqkv, const float* __restrict__ Wq,
    const float* __restrict__ Wa1, const float* __restrict__ Wa2,
    const float* __restrict__ Wproj,
    const float* __restrict__ bqkv, const float* __restrict__ bq)
{
    const int i = blockIdx.x * 256 + threadIdx.x;
    if (i < 32768) {
        float v = (i < 24576) ? Wqkv[i] : Wq[i - 24576];
        split1(v, g_w1h, g_w1l, i);
    } else if (i < 36864) {
        split1(Wa1[i - 32768], g_wa1h, g_wa1l, i - 32768);
    } else if (i < 40960) {
        split1(Wa2[i - 36864], g_wa2h, g_wa2l, i - 36864);
    } else if (i < 57344) {
        split1(Wproj[i - 40960], g_wph, g_wpl, i - 40960);
    } else if (i < 57600) {
        const int j = i - 57344;
        g_b1[j] = (j < 192) ? bqkv[j] : bq[j - 192];
    }
}

// ---------------- x -> hi/lo bf16 + 8x8 avgpool (one pass) -------------------
__global__ void __launch_bounds__(256) cvtpool(
    const float* __restrict__ x, bf16* __restrict__ xh, bf16* __restrict__ xl,
    float* __restrict__ xp)
{
    const int plane = blockIdx.x;
    const int t = threadIdx.x;
    const int wi = t >> 4, wj = t & 15;
    const float* sp = x + (size_t)plane * HW + (wi * 8) * WW + wj * 8;
    bf16* oh = xh + (size_t)plane * HW + (wi * 8) * WW + wj * 8;
    bf16* ol = xl + (size_t)plane * HW + (wi * 8) * WW + wj * 8;

    float s = 0.f;
    #pragma unroll
    for (int r = 0; r < 8; r++) {
        const float4 a = *reinterpret_cast<const float4*>(sp + r * WW);
        const float4 b = *reinterpret_cast<const float4*>(sp + r * WW + 4);
        s += a.x + a.y + a.z + a.w + b.x + b.y + b.z + b.w;
        u32 h0, l0, h1, l1, h2, l2, h3, l3;
        split2(a.x, a.y, h0, l0); split2(a.z, a.w, h1, l1);
        split2(b.x, b.y, h2, l2); split2(b.z, b.w, h3, l3);
        *reinterpret_cast<uint4*>(oh + r * WW) = make_uint4(h0, h1, h2, h3);
        *reinterpret_cast<uint4*>(ol + r * WW) = make_uint4(l0, l1, l2, l3);
    }
    xp[(size_t)plane * 256 + wi * 16 + wj] = s * (1.f / 64.f);
}

// ---------------- depthwise 3x3, smem-tiled rolling stencil -----------------
__global__ void __launch_bounds__(128) dwconv_qk(
    const float* __restrict__ qkv, const float* __restrict__ w,
    const float* __restrict__ bias,
    bf16* __restrict__ qkh, bf16* __restrict__ qkl,
    float* __restrict__ vout)
{
    const int z = blockIdx.z;
    const int b = z >> 7, t = z & 127;
    const int x = threadIdx.x;
    const int y0 = blockIdx.y * 16;

    __shared__ float s0[18][136];
    __shared__ float s1[18][136];

    if (t < 64) {
        const float* pq = qkv + ((size_t)b * 192 + t) * HW;
        const float* pk = qkv + ((size_t)b * 192 + 64 + t) * HW;
        #pragma unroll
        for (int r = 0; r < 18; r++) {
            const int yy = y0 - 1 + r;
            const bool ok = (yy >= 0) && (yy < HH);
            s0[r][x + 1] = ok ? __ldg(pq + yy * WW + x) : 0.f;
            s1[r][x + 1] = ok ? __ldg(pk + yy * WW + x) : 0.f;
        }
        if (x < 2) {
            const int col = x ? 129 : 0;
            #pragma unroll
            for (int r = 0; r < 18; r++) { s0[r][col] = 0.f; s1[r][col] = 0.f; }
        }
        __syncthreads();

        float wq[9], wk[9];
        #pragma unroll
        for (int i = 0; i < 9; i++) {
            wq[i] = __ldg(&w[t * 9 + i]);
            wk[i] = __ldg(&w[(64 + t) * 9 + i]);
        }
        const float bq = __ldg(&bias[t]);
        const float bk = __ldg(&bias[64 + t]);

        bf16* oh = qkh + ((size_t)b * 64 + t) * HW + (size_t)y0 * WW + x;
        bf16* ol = qkl + ((size_t)b * 64 + t) * HW + (size_t)y0 * WW + x;

        float Aq = 0.f, Bq = 0.f, Ak = 0.f, Bk = 0.f;
        #pragma unroll
        for (int r = 0; r < 18; r++) {
            const float lq = s0[r][x], cq = s0[r][x + 1], rq = s0[r][x + 2];
            const float h0q = wq[0]*lq + wq[1]*cq + wq[2]*rq;
            const float h1q = wq[3]*lq + wq[4]*cq + wq[5]*rq;
            const float h2q = wq[6]*lq + wq[7]*cq + wq[8]*rq;
            const float lk = s1[r][x], ck = s1[r][x + 1], rk = s1[r][x + 2];
            const float h0k = wk[0]*lk + wk[1]*ck + wk[2]*rk;
            const float h1k = wk[3]*lk + wk[4]*ck + wk[5]*rk;
            const float h2k = wk[6]*lk + wk[7]*ck + wk[8]*rk;
            Aq += h2q; Ak += h2k;
            if (r >= 2) {
                const int o = r - 2;
                const float prod = (Aq + bq) * (Ak + bk);
                const bf16 hv = __float2bfloat16(prod);
                oh[o * WW] = hv;
                ol[o * WW] = __float2bfloat16(prod - __bfloat162float(hv));
            }
            Aq = Bq + h1q; Bq = h0q;
            Ak = Bk + h1k; Bk = h0k;
        }
    } else {
        const int cv = t - 64;
        const float* pv = qkv + ((size_t)b * 192 + 128 + cv) * HW;
        #pragma unroll
        for (int r = 0; r < 18; r++) {
            const int yy = y0 - 1 + r;
            s0[r][x + 1] = (yy >= 0 && yy < HH) ? __ldg(pv + yy * WW + x) : 0.f;
        }
        if (x < 2) {
            const int col = x ? 129 : 0;
            #pragma unroll
            for (int r = 0; r < 18; r++) s0[r][col] = 0.f;
        }
        __syncthreads();

        float wv[9];
        #pragma unroll
        for (int i = 0; i < 9; i++) wv[i] = __ldg(&w[(128 + cv) * 9 + i]);
        const float bv = __ldg(&bias[128 + cv]);

        float* ov = vout + ((size_t)b * 64 + cv) * HW + (size_t)y0 * WW + x;
        float A = 0.f, Bv = 0.f;
        #pragma unroll
        for (int r = 0; r < 18; r++) {
            const float lv = s0[r][x], cvv = s0[r][x + 1], rv = s0[r][x + 2];
            const float h0 = wv[0]*lv + wv[1]*cvv + wv[2]*rv;
            const float h1 = wv[3]*lv + wv[4]*cvv + wv[5]*rv;
            const float h2 = wv[6]*lv + wv[7]*cvv + wv[8]*rv;
            A += h2;
            if (r >= 2) ov[(r - 2) * WW] = A + bv;
            A = Bv + h1; Bv = h0;
        }
    }
}

// ---------------- kv = Wkv @ xp + bkv (SIMT, fp32) ---------------------------
__global__ void __launch_bounds__(256) kv_simt(
    const float* __restrict__ xp, const float* __restrict__ Wkv,
    const float* __restrict__ bkv, float* __restrict__ kvout)
{
    const int idx = blockIdx.x * 256 + threadIdx.x;
    const int p  = idx & 255;
    const int oc = (idx >> 8) & 127;
    const int b  = idx >> 15;
    const float* xpb = xp + (size_t)b * 128 * 256 + p;
    const float* wr  = Wkv + oc * 128;
    float acc = __ldg(&bkv[oc]);
    #pragma unroll 8
    for (int c = 0; c < 128; c++)
        acc += __ldg(wr + c) * __ldg(xpb + c * 256);
    kvout[((size_t)b * 128 + oc) * 256 + p] = acc;
}

// ---------------- low-freq softmax attention (2 px/thread) -------------------
__global__ void __launch_bounds__(128) lowfreq_attn(
    const float* __restrict__ qg, const float* __restrict__ kv,
    bf16* __restrict__ ch, bf16* __restrict__ cl)
{
    const int b = blockIdx.z, h = blockIdx.y;
    const int p = blockIdx.x * 256 + threadIdx.x;

    __shared__ __align__(16) u64 ks2[256][8];
    __shared__ __align__(16) u64 vs2[256][8];

    const float* kvb = kv + (size_t)b * 128 * 256;
    for (int i = threadIdx.x; i < 2048; i += 128) {
        const int d2 = i >> 8, m = i & 255;
        ks2[m][d2] = pack2(kvb[(h * 16 + 2 * d2) * 256 + m],
                           kvb[(h * 16 + 2 * d2 + 1) * 256 + m]);
        vs2[m][d2] = pack2(kvb[(64 + h * 16 + 2 * d2) * 256 + m],
                           kvb[(64 + h * 16 + 2 * d2 + 1) * 256 + m]);
    }
    __syncthreads();

    u64 qa[8], qb[8];
    #pragma unroll
    for (int d2 = 0; d2 < 8; d2++) {
        const size_t base = (size_t)b * 64 * HW + (size_t)(h * 16 + 2 * d2) * HW + p;
        qa[d2] = pack2(0.25f * __ldg(&qg[base]),       0.25f * __ldg(&qg[base + HW]));
        qb[d2] = pack2(0.25f * __ldg(&qg[base + 128]), 0.25f * __ldg(&qg[base + HW + 128]));
    }

    float suma = 0.f, sumb = 0.f;
    u64 acca[8], accb[8];
    #pragma unroll
    for (int d2 = 0; d2 < 8; d2++) { acca[d2] = 0ull; accb[d2] = 0ull; }

    for (int m = 0; m < 256; m++) {
        u64 sa = 0ull, sb = 0ull;
        #pragma unroll
        for (int d2 = 0; d2 < 8; d2++) {
            const u64 kk = ks2[m][d2];
            sa = ffma2(qa[d2], kk, sa);
            sb = ffma2(qb[d2], kk, sb);
        }
        float a0, a1, b0, b1;
        unpack2(sa, a0, a1); unpack2(sb, b0, b1);
        const float ea = __expf(a0 + a1);
        const float eb = __expf(b0 + b1);
        suma += ea; sumb += eb;
        const u64 ea2 = pack2(ea, ea), eb2 = pack2(eb, eb);
        #pragma unroll
        for (int d2 = 0; d2 < 8; d2++) {
            const u64 vv = vs2[m][d2];
            acca[d2] = ffma2(ea2, vv, acca[d2]);
            accb[d2] = ffma2(eb2, vv, accb[d2]);
        }
    }

    const float inva = 1.f / suma, invb = 1.f / sumb;
    #pragma unroll
    for (int d2 = 0; d2 < 8; d2++) {
        float lo, hi;
        unpack2(acca[d2], lo, hi);
        const size_t base = ((size_t)b * 128 + 64 + h * 16 + 2 * d2) * HW + p;
        split1(lo * inva, ch, cl, base);
        split1(hi * inva, ch, cl, base + HW);
        unpack2(accb[d2], lo, hi);
        split1(lo * invb, ch, cl, base + 128);
        split1(hi * invb, ch, cl, base + HW + 128);
    }
}

// ---------------- launch -----------------------------------------------------
extern "C" void kernel_launch(void* const* d_in, const int* in_sizes, int n_in,
                              void* d_out, int out_size)
{
    const float* x     = (const float*)d_in[0];
    const float* Wqkv  = (const float*)d_in[1];
    const float* bqkv  = (const float*)d_in[2];
    const float* Wdw   = (const float*)d_in[3];
    const float* bdw   = (const float*)d_in[4];
    const float* Wa1   = (const float*)d_in[5];
    const float* ba1   = (const float*)d_in[6];
    const float* Wa2   = (const float*)d_in[7];
    const float* ba2   = (const float*)d_in[8];
    const float* Wq    = (const float*)d_in[9];
    const float* bq    = (const float*)d_in[10];
    const float* Wkv   = (const float*)d_in[11];
    const float* bkv   = (const float*)d_in[12];
    const float* Wproj = (const float*)d_in[13];
    const float* bproj = (const float*)d_in[14];
    float* out = (float*)d_out;

    float *qkv, *v, *qg, *kv, *xp, *b1;
    bf16 *xh, *xl, *qkh, *qkl, *ch, *cl;
    bf16 *w1h, *w1l, *wph, *wpl;
    cudaGetSymbolAddress((void**)&qkv, g_qkv);
    cudaGetSymbolAddress((void**)&v,   g_v);
    cudaGetSymbolAddress((void**)&qg,  g_qg);
    cudaGetSymbolAddress((void**)&kv,  g_kv);
    cudaGetSymbolAddress((void**)&xp,  g_xp);
    cudaGetSymbolAddress((void**)&b1,  g_b1);
    cudaGetSymbolAddress((void**)&xh,  g_xh);
    cudaGetSymbolAddress((void**)&xl,  g_xl);
    cudaGetSymbolAddress((void**)&qkh, g_qkh);
    cudaGetSymbolAddress((void**)&qkl, g_qkl);
    cudaGetSymbolAddress((void**)&ch,  g_ch);
    cudaGetSymbolAddress((void**)&cl,  g_cl);
    cudaGetSymbolAddress((void**)&w1h, g_w1h);
    cudaGetSymbolAddress((void**)&w1l, g_w1l);
    cudaGetSymbolAddress((void**)&wph, g_wph);
    cudaGetSymbolAddress((void**)&wpl, g_wpl);

    cudaFuncSetAttribute(gemm_bf16<true>,
                         cudaFuncAttributeMaxDynamicSharedMemorySize, SMEM_BYTES);
    cudaFuncSetAttribute(gemm_bf16<false>,
                         cudaFuncAttributeMaxDynamicSharedMemorySize, SMEM_BYTES);
    cudaFuncSetAttribute(fused_a1a2,
                         cudaFuncAttributeMaxDynamicSharedMemorySize, F2SMEM);

    // side stream + events (created once, outside graph capture)
    static cudaStream_t s1 = nullptr;
    static cudaEvent_t e1 = nullptr, e2 = nullptr, e3 = nullptr;
    if (!s1) {
        cudaStreamCreateWithFlags(&s1, cudaStreamNonBlocking);
        cudaEventCreateWithFlags(&e1, cudaEventDisableTiming);
        cudaEventCreateWithFlags(&e2, cudaEventDisableTiming);
        cudaEventCreateWithFlags(&e3, cudaEventDisableTiming);
    }

    // 0) weight prep + x split/pool (main stream)
    prep_weights<<<225, 256>>>(Wqkv, Wq, Wa1, Wa2, Wproj, bqkv, bq);
    cvtpool<<<NB * 128, 256>>>(x, xh, xl, xp);
    cudaEventRecord(e1, 0);

    // 1) fused qkv+qg GEMM (main)
    gemm_bf16<true><<<dim3(HW / 256, 4, NB), 256, SMEM_BYTES>>>(
        xh, xl, w1h, w1l, b1, 128, HW,
        qkv, 192 * HW, qg, 64 * HW, 192);
    cudaEventRecord(e2, 0);

    // side branch: kv then attention (overlaps dwconv + fused_a1a2)
    cudaStreamWaitEvent(s1, e1, 0);
    kv_simt<<<NB * 128 * 256 / 256, 256, 0, s1>>>(xp, Wkv, bkv, kv);
    cudaStreamWaitEvent(s1, e2, 0);
    lowfreq_attn<<<dim3(HW / 256, 4, NB), 128, 0, s1>>>(qg, kv, ch, cl);
    cudaEventRecord(e3, s1);

    // 2) depthwise 3x3 with q*k fusion (main)
    dwconv_qk<<<dim3(1, 8, NB * 128), 128>>>(qkv, Wdw, bdw, qkh, qkl, v);

    // 3+4) fused a1 -> swish -> a2 -> tanh*v (main) -> cat planes [0,64)
    fused_a1a2<<<dim3(HW / 128, NB), 256, F2SMEM>>>(qkh, qkl, ba1, ba2, v, ch, cl);

    // join, then 5) out = Wproj @ cat
    cudaStreamWaitEvent(0, e3, 0);
    gemm_bf16<false><<<dim3(HW / 256, 2, NB), 256, SMEM_BYTES>>>(
        ch, cl, wph, wpl, bproj, 128, HW,
        out, 128 * HW, nullptr, 0, 0);
}